// round 10
// baseline (speedup 1.0000x reference)
#include <cuda_runtime.h>
#include <cmath>

// ---------------------------------------------------------------------------
// SceneSegCNNTRM round 7: BK=32 fragment-ordered tf32 mma GEMM (all BM=64
// tiles, bigger grids), conv folded into K, smem-cached pooling, cls head.
// ---------------------------------------------------------------------------

#define MROWS   4096
#define NB      1024
#define DIN     2048
#define DMODEL  640
#define NLAYER  6
#define QKVN    1920

__device__ __align__(256) float g_pooled[MROWS * DIN];
__device__ __align__(256) float g_out   [MROWS * DMODEL];
__device__ __align__(256) float g_qkv   [MROWS * QKVN];
__device__ __align__(256) float g_wqkv  [NLAYER * DMODEL * QKVN];
__device__ __align__(256) float g_ctx   [MROWS * DMODEL];
__device__ __align__(256) float g_tmp   [MROWS * DMODEL];
__device__ __align__(256) float g_ff    [MROWS * 128];
__device__ __align__(256) float g_h     [MROWS * 256];

// ---------------------------------------------------------------------------
__global__ __launch_bounds__(256) void pack_qkv_kernel(
    const float* __restrict__ Wq, const float* __restrict__ Wk,
    const float* __restrict__ Wv, float* __restrict__ out)
{
    const int i = blockIdx.x * 256 + threadIdx.x;
    if (i >= NLAYER * DMODEL * QKVN) return;
    const int n = i % QKVN;
    const int k = (i / QKVN) % DMODEL;
    const int l = i / (QKVN * DMODEL);
    const float* W = (n < DMODEL) ? Wq : (n < 2 * DMODEL) ? Wk : Wv;
    out[i] = W[(size_t)l * DMODEL * DMODEL + (size_t)k * DMODEL + (n % DMODEL)];
}

// ---------------------------------------------------------------------------
// pool + cos-sim: x window cached in 64KB dynamic smem (single global read).
// ---------------------------------------------------------------------------
__global__ __launch_bounds__(256) void pool_sim_kernel(
    const float* __restrict__ x,
    const float* __restrict__ cos_w, const float* __restrict__ cos_b,
    const float* __restrict__ attn_w, const float* __restrict__ attn_b,
    float* __restrict__ pooled, float* __restrict__ outbuf)
{
    extern __shared__ float xs[];   // [8][2048]
    const int m   = blockIdx.x;
    const int tid = threadIdx.x;
    const float* xr = x + (size_t)m * 8 * DIN;

#pragma unroll
    for (int r = 0; r < 16; r++) {
        const int idx = tid + r * 256;
        *reinterpret_cast<float4*>(xs + idx * 4) =
            *reinterpret_cast<const float4*>(xr + idx * 4);
    }
    __syncthreads();

    float g12[16], g11[10], g22[10], sw[8], ad[8];
#pragma unroll
    for (int i = 0; i < 16; i++) g12[i] = 0.f;
#pragma unroll
    for (int i = 0; i < 10; i++) { g11[i] = 0.f; g22[i] = 0.f; }
#pragma unroll
    for (int i = 0; i < 8; i++)  { sw[i] = 0.f; ad[i] = 0.f; }

    for (int d = tid; d < DIN; d += 256) {
        float xv[8];
#pragma unroll
        for (int w = 0; w < 8; w++) xv[w] = xs[w * DIN + d];
        const float aw = attn_w[d];
#pragma unroll
        for (int w = 0; w < 8; w++) { sw[w] += xv[w]; ad[w] += xv[w] * aw; }
#pragma unroll
        for (int i = 0; i < 4; i++)
#pragma unroll
            for (int j = 0; j < 4; j++)
                g12[i * 4 + j] += xv[i] * xv[4 + j];
#pragma unroll
        for (int i = 0; i < 4; i++)
#pragma unroll
            for (int j = i; j < 4; j++) {
                const int t = i * (7 - i) / 2 + j;
                g11[t] += xv[i] * xv[j];
                g22[t] += xv[4 + i] * xv[4 + j];
            }
    }

    __shared__ float red[52][8];
    __shared__ float fin[52];
    __shared__ float aprob[8];
    const int lane = tid & 31, wid = tid >> 5;

#define WREDUCE(arr, n, off)                                              \
    _Pragma("unroll")                                                     \
    for (int i = 0; i < n; i++) {                                         \
        float v = arr[i];                                                 \
        _Pragma("unroll")                                                 \
        for (int o = 16; o; o >>= 1) v += __shfl_xor_sync(0xffffffffu, v, o); \
        if (lane == 0) red[off + i][wid] = v;                             \
    }
    WREDUCE(g12, 16, 0)
    WREDUCE(g11, 10, 16)
    WREDUCE(g22, 10, 26)
    WREDUCE(sw,   8, 36)
    WREDUCE(ad,   8, 44)
#undef WREDUCE
    __syncthreads();
    if (tid < 52) {
        float t = 0.f;
#pragma unroll
        for (int w = 0; w < 8; w++) t += red[tid][w];
        fin[tid] = t;
    }
    __syncthreads();

    if (tid == 0) {
        const float ab = attn_b[0];
        float sc[8], mx = -1e30f;
#pragma unroll
        for (int w = 0; w < 8; w++) { sc[w] = fin[44 + w] + ab; mx = fmaxf(mx, sc[w]); }
        float s = 0.f;
#pragma unroll
        for (int w = 0; w < 8; w++) { sc[w] = expf(sc[w] - mx); s += sc[w]; }
        const float inv = 1.f / s;
#pragma unroll
        for (int w = 0; w < 8; w++) aprob[w] = sc[w] * inv;
    }

    if (tid < 128) {
        float cw[4];
#pragma unroll
        for (int w = 0; w < 4; w++) cw[w] = cos_w[tid * 4 + w];
        const float cb = cos_b[tid];
        float d12 = 0.f, q1 = 0.f, q2 = 0.f, cs1 = 0.f, cs2 = 0.f;
#pragma unroll
        for (int i = 0; i < 4; i++)
#pragma unroll
            for (int j = 0; j < 4; j++)
                d12 += cw[i] * cw[j] * fin[i * 4 + j];
#pragma unroll
        for (int i = 0; i < 4; i++)
#pragma unroll
            for (int j = i; j < 4; j++) {
                const int t = i * (7 - i) / 2 + j;
                const float c2 = cw[i] * cw[j] * ((i == j) ? 1.f : 2.f);
                q1 += c2 * fin[16 + t];
                q2 += c2 * fin[26 + t];
            }
#pragma unroll
        for (int w = 0; w < 4; w++) {
            cs1 += cw[w] * fin[36 + w];
            cs2 += cw[w] * fin[40 + w];
        }
        d12 += cb * (cs1 + cs2) + (float)DIN * cb * cb;
        q1  += 2.f * cb * cs1 + (float)DIN * cb * cb;
        q2  += 2.f * cb * cs2 + (float)DIN * cb * cb;
        const float n1 = fmaxf(sqrtf(q1), 1e-8f);
        const float n2 = fmaxf(sqrtf(q2), 1e-8f);
        outbuf[(size_t)m * DMODEL + 512 + tid] = d12 / (n1 * n2);
    }
    __syncthreads();

    float a[8];
#pragma unroll
    for (int w = 0; w < 8; w++) a[w] = aprob[w];
    for (int d = tid; d < DIN; d += 256) {
        float p = 0.f;
#pragma unroll
        for (int w = 0; w < 8; w++) p += a[w] * xs[w * DIN + d];
        pooled[(size_t)m * DIN + d] = p;
    }
}

// ---------------------------------------------------------------------------
// tf32 tensor-core GEMM, fragment-ordered smem, BK=32 double-buffered.
//  - CONV=true: virtual K' = 3*Kreal; tap t = k'/Kreal shifts A rows (+t-1)
//    within each NB-row batch; B gathered from (Cout, Cin, 3) weights.
//  - Requires: M%BM==0, N%BN==0, K%32==0, non-conv B has unit n-stride.
//  - flags: bit0 = relu.
// ---------------------------------------------------------------------------
__device__ __forceinline__ float to_tf32(float x) {
    asm("cvt.rna.tf32.f32 %0, %0;" : "+f"(x));
    return x;
}

template<int BM, int BN, bool CONV>
__global__ __launch_bounds__(256) void gemm_tc(
    const float* __restrict__ A, int lda,
    const float* __restrict__ B, int ldbK,
    const float* __restrict__ bias,
    float* __restrict__ C, int ldc,
    int M, int N, int K, int klog2, int flags)
{
    constexpr int MTB = BM / 16;           // m-tiles per block
    constexpr int NTB = BN / 8;            // n-tiles per block
    constexpr int WARPS_N = 8 / (BM / 32);
    constexpr int WN  = BN / WARPS_N;
    constexpr int NT  = WN / 8;            // n-tiles per warp
    constexpr int A4  = BM / 32;           // float4 A-loads / thread / stage
    constexpr int B4  = BN / 32;           // float4 B-loads (vec path)
    constexpr int BSC = BN / 8;            // scalar B-loads (conv path)

    __shared__ float As[2][BM * 32];
    __shared__ float Bs[2][BN * 32];

    const int tid  = threadIdx.x;
    const int lane = tid & 31;
    const int w    = tid >> 5;
    const int bm   = blockIdx.y * BM;
    const int bn   = blockIdx.x * BN;
    const int mtw  = (w / WARPS_N) * 2;          // warp's first m-tile
    const int ntw  = ((w % WARPS_N) * WN) >> 3;  // warp's first n-tile

    float acc[2][NT][4];
#pragma unroll
    for (int i = 0; i < 2; i++)
#pragma unroll
        for (int j = 0; j < NT; j++)
#pragma unroll
            for (int r = 0; r < 4; r++) acc[i][j][r] = 0.f;

    float4 ra[A4];
    float4 rbv[B4];
    float  rbs[BSC];
    const int kmask = CONV ? ((1 << klog2) - 1) : 0;

    auto loadA = [&](int k0) {
        const int t   = CONV ? (k0 >> klog2) : 0;
        const int kr0 = CONV ? (k0 & kmask) : k0;
#pragma unroll
        for (int r = 0; r < A4; r++) {
            const int idx = tid + r * 256;
            const int mm  = idx >> 3, cg = (idx & 7) << 2;   // 8 float4 per 32-f row
            const int gm  = bm + mm;
            float4 v = make_float4(0.f, 0.f, 0.f, 0.f);
            if (!CONV) {
                v = *reinterpret_cast<const float4*>(A + (size_t)gm * lda + kr0 + cg);
            } else if ((unsigned)((gm & (NB - 1)) + t - 1) < (unsigned)NB) {
                v = *reinterpret_cast<const float4*>(A + (size_t)(gm + t - 1) * lda + kr0 + cg);
            }
            ra[r] = v;
        }
    };
    auto storeA = [&](int st) {
#pragma unroll
        for (int r = 0; r < A4; r++) {
            const int idx = tid + r * 256;
            const int mm  = idx >> 3, cg = (idx & 7) << 2;
            const int kb  = cg >> 3, kh = (cg >> 2) & 1;     // kb in 0..3
            const int mtile = mm >> 4, g = mm & 7, hi = (mm >> 3) & 1;
            float* p = &As[st][(kb * MTB + mtile) * 128 + g * 16 + hi + 2 * kh];
            p[0]  = to_tf32(ra[r].x);
            p[4]  = to_tf32(ra[r].y);
            p[8]  = to_tf32(ra[r].z);
            p[12] = to_tf32(ra[r].w);
        }
    };
    auto loadB = [&](int k0) {
        if (!CONV) {
#pragma unroll
            for (int r = 0; r < B4; r++) {
                const int idx = tid + r * 256;
                const int kk  = idx / (BN / 4);
                const int nn  = (idx % (BN / 4)) * 4;
                rbv[r] = *reinterpret_cast<const float4*>(
                    B + (size_t)(k0 + kk) * ldbK + bn + nn);
            }
        } else {
            const int t   = k0 >> klog2;
            const int kr0 = k0 & kmask;
            const int kr3 = 3 << klog2;
#pragma unroll
            for (int r = 0; r < BSC; r++) {
                const int idx = tid + r * 256;
                const int kk  = idx / BN;
                const int nn  = idx % BN;
                rbs[r] = B[(size_t)(bn + nn) * kr3 + (size_t)(kr0 + kk) * 3 + t];
            }
        }
    };
    auto storeB = [&](int st) {
        if (!CONV) {
#pragma unroll
            for (int r = 0; r < B4; r++) {
                const int idx = tid + r * 256;
                const int kk  = idx / (BN / 4);
                const int nn  = (idx % (BN / 4)) * 4;
                const int kb  = kk >> 3, tg = kk & 3, kh = (kk >> 2) & 1;
                const float vv[4] = { rbv[r].x, rbv[r].y, rbv[r].z, rbv[r].w };
#pragma unroll
                for (int j = 0; j < 4; j++) {
                    const int n = nn + j;
                    Bs[st][(kb * NTB + (n >> 3)) * 64 + ((n & 7) * 4 + tg) * 2 + kh]
                        = to_tf32(vv[j]);
                }
            }
        } else {
#pragma unroll
            for (int r = 0; r < BSC; r++) {
                const int idx = tid + r * 256;
                const int kk  = idx / BN;
                const int n   = idx % BN;
                const int kb  = kk >> 3, tg = kk & 3, kh = (kk >> 2) & 1;
                Bs[st][(kb * NTB + (n >> 3)) * 64 + ((n & 7) * 4 + tg) * 2 + kh]
                    = to_tf32(rbs[r]);
            }
        }
    };

    loadA(0); loadB(0);
    storeA(0); storeB(0);
    __syncthreads();

    int st = 0;
    for (int k0 = 0; k0 < K; k0 += 32) {
        const bool more = (k0 + 32) < K;
        if (more) { loadA(k0 + 32); loadB(k0 + 32); }

#pragma unroll
        for (int kb = 0; kb < 4; kb++) {
            float4 af[2];
            float2 bf[NT];
#pragma unroll
            for (int mi = 0; mi < 2; mi++)
                af[mi] = *reinterpret_cast<const float4*>(
                    &As[st][(kb * MTB + mtw + mi) * 128 + lane * 4]);
#pragma unroll
            for (int nj = 0; nj < NT; nj++)
                bf[nj] = *reinterpret_cast<const float2*>(
                    &Bs[st][(kb * NTB + ntw + nj) * 64 + lane * 2]);
#pragma unroll
            for (int mi = 0; mi < 2; mi++)
#pragma unroll
                for (int nj = 0; nj < NT; nj++)
                    asm volatile(
                        "mma.sync.aligned.m16n8k8.row.col.f32.tf32.tf32.f32 "
                        "{%0,%1,%2,%3}, {%4,%5,%6,%7}, {%8,%9}, {%0,%1,%2,%3};\n"
                        : "+f"(acc[mi][nj][0]), "+f"(acc[mi][nj][1]),
                          "+f"(acc[mi][nj][2]), "+f"(acc[mi][nj][3])
                        : "r"(__float_as_uint(af[mi].x)), "r"(__float_as_uint(af[mi].y)),
                          "r"(__float_as_uint(af[mi].z)), "r"(__float_as_uint(af[mi].w)),
                          "r"(__float_as_uint(bf[nj].x)), "r"(__float_as_uint(bf[nj].y)));
        }

        if (more) {
            storeA(st ^ 1); storeB(st ^ 1);
            __syncthreads();
            st ^= 1;
        }
    }

    const int g  = lane >> 2, tg = lane & 3;
#pragma unroll
    for (int mi = 0; mi < 2; mi++) {
        const int r0 = bm + (mtw + mi) * 16 + g;
#pragma unroll
        for (int nj = 0; nj < NT; nj++) {
            const int c0 = bn + (ntw + nj) * 8 + tg * 2;
#pragma unroll
            for (int hh = 0; hh < 2; hh++) {
                float* crow = C + (size_t)(r0 + hh * 8) * ldc;
#pragma unroll
                for (int cc = 0; cc < 2; cc++) {
                    float v = acc[mi][nj][hh * 2 + cc];
                    if (bias) v += bias[c0 + cc];
                    if (flags & 1) v = fmaxf(v, 0.f);
                    crow[c0 + cc] = v;
                }
            }
        }
    }
}

// ---------------------------------------------------------------------------
// Banded local attention (|i-j|<=1), one warp per (token, head), d_head=80.
// ---------------------------------------------------------------------------
__global__ __launch_bounds__(256) void banded_attn_kernel(
    const float* __restrict__ qkv, float* __restrict__ ctx)
{
    const int gw   = (blockIdx.x * 256 + threadIdx.x) >> 5;
    const int lane = threadIdx.x & 31;
    if (gw >= MROWS * 8) return;
    const int m = gw >> 3;
    const int h = gw & 7;
    const int n = m & (NB - 1);
    const float scale = 0.11180339887498949f;

    const float* qp = qkv + (size_t)m * QKVN + h * 80;
    const float qv0 = qp[lane], qv1 = qp[lane + 32];
    const float qv2 = (lane < 16) ? qp[lane + 64] : 0.f;

    float s[3];
    bool  val[3];
#pragma unroll
    for (int j = 0; j < 3; j++) {
        const int nn = n + j - 1;
        val[j] = (nn >= 0 && nn < NB);
        float acc = 0.f;
        if (val[j]) {
            const float* kp = qkv + (size_t)(m + j - 1) * QKVN + DMODEL + h * 80;
            acc = qv0 * kp[lane] + qv1 * kp[lane + 32];
            if (lane < 16) acc += qv2 * kp[lane + 64];
        }
#pragma unroll
        for (int o = 16; o; o >>= 1) acc += __shfl_xor_sync(0xffffffffu, acc, o);
        s[j] = val[j] ? acc * scale : -1e30f;
    }

    const float mx = fmaxf(s[0], fmaxf(s[1], s[2]));
    float e[3], sum = 0.f;
#pragma unroll
    for (int j = 0; j < 3; j++) {
        e[j] = val[j] ? expf(s[j] - mx) : 0.f;
        sum += e[j];
    }
    const float inv = 1.f / sum;

    float o0 = 0.f, o1 = 0.f, o2 = 0.f;
#pragma unroll
    for (int j = 0; j < 3; j++) {
        if (!val[j]) continue;
        const float p = e[j] * inv;
        const float* vp = qkv + (size_t)(m + j - 1) * QKVN + 2 * DMODEL + h * 80;
        o0 += p * vp[lane];
        o1 += p * vp[lane + 32];
        if (lane < 16) o2 += p * vp[lane + 64];
    }
    float* cp = ctx + (size_t)m * DMODEL + h * 80;
    cp[lane] = o0;
    cp[lane + 32] = o1;
    if (lane < 16) cp[lane + 64] = o2;
}

// ---------------------------------------------------------------------------
__global__ __launch_bounds__(256) void residual_ln_kernel(
    float* __restrict__ out, const float* __restrict__ add,
    const float* __restrict__ g, const float* __restrict__ b)
{
    const int m = blockIdx.x;
    const int tid = threadIdx.x;
    const int lane = tid & 31, wid = tid >> 5;
    __shared__ float red[8];
    __shared__ float mean_s, rstd_s;

    float v[3];
    float s = 0.f;
#pragma unroll
    for (int i = 0; i < 3; i++) {
        const int d = tid + i * 256;
        float t = 0.f;
        if (d < DMODEL) t = out[(size_t)m * DMODEL + d] + add[(size_t)m * DMODEL + d];
        v[i] = t;
        s += t;
    }
#pragma unroll
    for (int o = 16; o; o >>= 1) s += __shfl_xor_sync(0xffffffffu, s, o);
    if (lane == 0) red[wid] = s;
    __syncthreads();
    if (tid == 0) {
        float t = 0.f;
#pragma unroll
        for (int w = 0; w < 8; w++) t += red[w];
        mean_s = t / (float)DMODEL;
    }
    __syncthreads();
    const float mean = mean_s;

    float vs = 0.f;
#pragma unroll
    for (int i = 0; i < 3; i++) {
        const int d = tid + i * 256;
        if (d < DMODEL) { const float dd = v[i] - mean; vs += dd * dd; }
    }
#pragma unroll
    for (int o = 16; o; o >>= 1) vs += __shfl_xor_sync(0xffffffffu, vs, o);
    __syncthreads();
    if (lane == 0) red[wid] = vs;
    __syncthreads();
    if (tid == 0) {
        float t = 0.f;
#pragma unroll
        for (int w = 0; w < 8; w++) t += red[w];
        rstd_s = rsqrtf(t / (float)DMODEL + 1e-5f);
    }
    __syncthreads();
    const float rstd = rstd_s;
#pragma unroll
    for (int i = 0; i < 3; i++) {
        const int d = tid + i * 256;
        if (d < DMODEL)
            out[(size_t)m * DMODEL + d] = (v[i] - mean) * rstd * g[d] + b[d];
    }
}

// ---------------------------------------------------------------------------
// cls head: logits[m, 0..1] = h[m, :256] @ cls_w + cls_b. One warp per row.
// ---------------------------------------------------------------------------
__global__ __launch_bounds__(256) void cls_kernel(
    const float* __restrict__ h, const float* __restrict__ w,
    const float* __restrict__ b, float* __restrict__ out)
{
    const int gw   = (blockIdx.x * 256 + threadIdx.x) >> 5;
    const int lane = threadIdx.x & 31;
    if (gw >= MROWS) return;
    float a0 = 0.f, a1 = 0.f;
#pragma unroll
    for (int i = 0; i < 8; i++) {
        const int k = lane + i * 32;
        const float hv = h[(size_t)gw * 256 + k];
        a0 += hv * w[k * 2];
        a1 += hv * w[k * 2 + 1];
    }
#pragma unroll
    for (int o = 16; o; o >>= 1) {
        a0 += __shfl_xor_sync(0xffffffffu, a0, o);
        a1 += __shfl_xor_sync(0xffffffffu, a1, o);
    }
    if (lane == 0) {
        out[(size_t)gw * 2]     = a0 + b[0];
        out[(size_t)gw * 2 + 1] = a1 + b[1];
    }
}

// ---------------------------------------------------------------------------
extern "C" void kernel_launch(void* const* d_in, const int* in_sizes, int n_in,
                              void* d_out, int out_size)
{
    const float* x       = (const float*)d_in[0];
    const float* cos_w   = (const float*)d_in[2];
    const float* cos_b   = (const float*)d_in[3];
    const float* attn_w  = (const float*)d_in[4];
    const float* attn_b  = (const float*)d_in[5];
    const float* conv1_w = (const float*)d_in[6];
    const float* conv1_b = (const float*)d_in[7];
    const float* conv2_w = (const float*)d_in[8];
    const float* conv2_b = (const float*)d_in[9];
    const float* Wq      = (const float*)d_in[10];
    const float* Wk      = (const float*)d_in[11];
    const float* Wv      = (const float*)d_in[12];
    const float* Wo      = (const float*)d_in[13];
    const float* ln1_g   = (const float*)d_in[14];
    const float* ln1_b   = (const float*)d_in[15];
    const float* ff1_w   = (const float*)d_in[16];
    const float* ff1_b   = (const float*)d_in[17];
    const float* ff2_w   = (const float*)d_in[18];
    const float* ff2_b   = (const float*)d_in[19];
    const float* ln2_g   = (const float*)d_in[20];
    const float* ln2_b   = (const float*)d_in[21];
    const float* fc_w    = (const float*)d_in[22];
    const float* fc_b    = (const float*)d_in[23];
    const float* cls_w   = (const float*)d_in[24];
    const float* cls_b   = (const float*)d_in[25];
    float* logits = (float*)d_out;

    float *pooled, *obuf, *qkvb, *wqkv, *ctxb, *tmpb, *ffb, *hb;
    cudaGetSymbolAddress((void**)&pooled, g_pooled);
    cudaGetSymbolAddress((void**)&obuf,   g_out);
    cudaGetSymbolAddress((void**)&qkvb,   g_qkv);
    cudaGetSymbolAddress((void**)&wqkv,   g_wqkv);
    cudaGetSymbolAddress((void**)&ctxb,   g_ctx);
    cudaGetSymbolAddress((void**)&tmpb,   g_tmp);
    cudaGetSymbolAddress((void**)&ffb,    g_ff);
    cudaGetSymbolAddress((void**)&hb,     g_h);

    // idempotent, deterministic, capture-safe; no static guard
    cudaFuncSetAttribute(pool_sim_kernel,
                         cudaFuncAttributeMaxDynamicSharedMemorySize, 65536);

    // 0. pack QKV weights
    {
        const int tot = NLAYER * DMODEL * QKVN;
        pack_qkv_kernel<<<(tot + 255) / 256, 256>>>(Wq, Wk, Wv, wqkv);
    }

    // 1. pooling + cos-sim
    pool_sim_kernel<<<MROWS, 256, 65536>>>(x, cos_w, cos_b, attn_w, attn_b,
                                           pooled, obuf);

    // 2. conv1 as one GEMM: K' = 3*2048 = 6144, tap folded into K
    gemm_tc<64, 64, true><<<dim3(4, 64), 256>>>(
        pooled, DIN, conv1_w, 0, conv1_b, obuf, DMODEL,
        MROWS, 256, 3 * DIN, 11, 1 /*relu*/);

    // 3. conv2: K' = 3*256 = 768
    gemm_tc<64, 64, true><<<dim3(4, 64), 256>>>(
        obuf, DMODEL, conv2_w, 0, conv2_b, obuf + 256, DMODEL,
        MROWS, 256, 3 * 256, 8, 1 /*relu*/);

    // 4. transformer layers
    for (int l = 0; l < NLAYER; l++) {
        gemm_tc<64, 128, false><<<dim3(15, 64), 256>>>(
            obuf, DMODEL, wqkv + (size_t)l * DMODEL * QKVN, QKVN,
            nullptr, qkvb, QKVN, MROWS, QKVN, DMODEL, 0, 0);

        banded_attn_kernel<<<MROWS, 256>>>(qkvb, ctxb);

        gemm_tc<64, 128, false><<<dim3(5, 64), 256>>>(
            ctxb, DMODEL, Wo + (size_t)l * DMODEL * DMODEL, DMODEL,
            nullptr, tmpb, DMODEL, MROWS, DMODEL, DMODEL, 0, 0);
        residual_ln_kernel<<<MROWS, 256>>>(obuf, tmpb,
                                           ln1_g + l * DMODEL, ln1_b + l * DMODEL);

        gemm_tc<64, 32, false><<<dim3(4, 64), 256>>>(
            obuf, DMODEL, ff1_w + (size_t)l * DMODEL * 128, 128,
            ff1_b + l * 128, ffb, 128, MROWS, 128, DMODEL, 0, 1 /*relu*/);
        gemm_tc<64, 128, false><<<dim3(5, 64), 256>>>(
            ffb, 128, ff2_w + (size_t)l * 128 * DMODEL, DMODEL,
            ff2_b + l * DMODEL, tmpb, DMODEL, MROWS, DMODEL, 128, 0, 0);
        residual_ln_kernel<<<MROWS, 256>>>(obuf, tmpb,
                                           ln2_g + l * DMODEL, ln2_b + l * DMODEL);
    }

    // 5. head
    gemm_tc<64, 64, false><<<dim3(4, 64), 256>>>(
        obuf, DMODEL, fc_w, 256, fc_b, hb, 256, MROWS, 256, DMODEL, 0, 1 /*relu*/);
    cls_kernel<<<(MROWS * 32 + 255) / 256, 256>>>(hb, cls_w, cls_b, logits);
}

// round 11
// speedup vs baseline: 5.1300x; 5.1300x over previous
#include <cuda_runtime.h>
#include <cmath>

// ---------------------------------------------------------------------------
// SceneSegCNNTRM round 10: conflict-free smem GEMM.
//  - B (weights) pre-packed in gmem into mma-fragment order -> linear STS
//  - A kept m-major with stride-36 padding -> conflict-free STS/LDS
//  - conv taps folded into K (A-shift; taps pre-folded in packed weights)
// ---------------------------------------------------------------------------

#define MROWS   4096
#define NB      1024
#define DIN     2048
#define DMODEL  640
#define NLAYER  6
#define QKVN    1920
#define ASTRIDE 36            // 36 mod 32 = 4 -> bank-conflict-free A frag reads

__device__ __align__(256) float g_pooled[MROWS * DIN];
__device__ __align__(256) float g_out   [MROWS * DMODEL];
__device__ __align__(256) float g_qkv   [MROWS * QKVN];
__device__ __align__(256) float g_ctx   [MROWS * DMODEL];
__device__ __align__(256) float g_tmp   [MROWS * DMODEL];
__device__ __align__(256) float g_ff    [MROWS * 128];
__device__ __align__(256) float g_h     [MROWS * 256];
// packed (fragment-ordered) weights
__device__ __align__(256) float g_wqkv[NLAYER * DMODEL * QKVN];
__device__ __align__(256) float g_wo  [NLAYER * DMODEL * DMODEL];
__device__ __align__(256) float g_wf1 [NLAYER * DMODEL * 128];
__device__ __align__(256) float g_wf2 [NLAYER * 128 * DMODEL];
__device__ __align__(256) float g_wfc [DMODEL * 256];
__device__ __align__(256) float g_wc1 [3 * DIN * 256];
__device__ __align__(256) float g_wc2 [3 * 256 * 256];

__device__ __forceinline__ float to_tf32(float x) {
    asm("cvt.rna.tf32.f32 %0, %0;" : "+f"(x));
    return x;
}

// fragment-order index for B[k][n] in an [K x N] matrix:
// 64-float block per (ktile=k/8, ntile=n/8); within block, lane l=(n&7)*4+(k&3)
// holds float2 {k, k+4} -> word ((n&7)*4+(k&3))*2 + ((k>>2)&1)
__device__ __forceinline__ size_t fidx(int k, int n, int N) {
    return ((size_t)(k >> 3) * (N >> 3) + (n >> 3)) * 64
         + (size_t)(((n & 7) * 4 + (k & 3)) * 2 + ((k >> 2) & 1));
}

// ---------------------------------------------------------------------------
// weight pack kernels (run every replay; deterministic)
// ---------------------------------------------------------------------------
__global__ __launch_bounds__(256) void pack_frag_kernel(
    const float* __restrict__ W, float* __restrict__ out, int K, int N, int L)
{
    const int i = blockIdx.x * 256 + threadIdx.x;
    if (i >= L * K * N) return;
    const int l = i / (K * N);
    const int rem = i - l * K * N;
    const int k = rem / N, n = rem - (rem / N) * N;
    out[(size_t)l * K * N + fidx(k, n, N)] = to_tf32(W[i]);
}

__global__ __launch_bounds__(256) void pack_qkv_kernel(
    const float* __restrict__ Wq, const float* __restrict__ Wk,
    const float* __restrict__ Wv, float* __restrict__ out)
{
    const int i = blockIdx.x * 256 + threadIdx.x;
    if (i >= NLAYER * DMODEL * QKVN) return;
    const int l = i / (DMODEL * QKVN);
    const int rem = i - l * DMODEL * QKVN;
    const int k = rem / QKVN, np = rem - k * QKVN;
    const float* W = (np < DMODEL) ? Wq : (np < 2 * DMODEL) ? Wk : Wv;
    const float v = W[(size_t)l * DMODEL * DMODEL + (size_t)k * DMODEL + (np % DMODEL)];
    out[(size_t)l * DMODEL * QKVN + fidx(k, np, QKVN)] = to_tf32(v);
}

// conv weights (N=Cout, K=Cin, 3) -> packed K' = 3K (tap-major)
__global__ __launch_bounds__(256) void pack_conv_kernel(
    const float* __restrict__ W, float* __restrict__ out, int K, int N)
{
    const int i = blockIdx.x * 256 + threadIdx.x;
    if (i >= N * K * 3) return;
    const int n = i / (K * 3);
    const int r = i - n * K * 3;
    const int k = r / 3, t = r - k * 3;
    out[fidx(t * K + k, n, N)] = to_tf32(W[i]);
}

// ---------------------------------------------------------------------------
// pool + cos-sim (unchanged; correct since R2)
// ---------------------------------------------------------------------------
__global__ __launch_bounds__(256) void pool_sim_kernel(
    const float* __restrict__ x,
    const float* __restrict__ cos_w, const float* __restrict__ cos_b,
    const float* __restrict__ attn_w, const float* __restrict__ attn_b,
    float* __restrict__ pooled, float* __restrict__ outbuf)
{
    extern __shared__ float xs[];   // [8][2048]
    const int m   = blockIdx.x;
    const int tid = threadIdx.x;
    const float* xr = x + (size_t)m * 8 * DIN;

#pragma unroll
    for (int r = 0; r < 16; r++) {
        const int idx = tid + r * 256;
        *reinterpret_cast<float4*>(xs + idx * 4) =
            *reinterpret_cast<const float4*>(xr + idx * 4);
    }
    __syncthreads();

    float g12[16], g11[10], g22[10], sw[8], ad[8];
#pragma unroll
    for (int i = 0; i < 16; i++) g12[i] = 0.f;
#pragma unroll
    for (int i = 0; i < 10; i++) { g11[i] = 0.f; g22[i] = 0.f; }
#pragma unroll
    for (int i = 0; i < 8; i++)  { sw[i] = 0.f; ad[i] = 0.f; }

    for (int d = tid; d < DIN; d += 256) {
        float xv[8];
#pragma unroll
        for (int w = 0; w < 8; w++) xv[w] = xs[w * DIN + d];
        const float aw = attn_w[d];
#pragma unroll
        for (int w = 0; w < 8; w++) { sw[w] += xv[w]; ad[w] += xv[w] * aw; }
#pragma unroll
        for (int i = 0; i < 4; i++)
#pragma unroll
            for (int j = 0; j < 4; j++)
                g12[i * 4 + j] += xv[i] * xv[4 + j];
#pragma unroll
        for (int i = 0; i < 4; i++)
#pragma unroll
            for (int j = i; j < 4; j++) {
                const int t = i * (7 - i) / 2 + j;
                g11[t] += xv[i] * xv[j];
                g22[t] += xv[4 + i] * xv[4 + j];
            }
    }

    __shared__ float red[52][8];
    __shared__ float fin[52];
    __shared__ float aprob[8];
    const int lane = tid & 31, wid = tid >> 5;

#define WREDUCE(arr, n, off)                                              \
    _Pragma("unroll")                                                     \
    for (int i = 0; i < n; i++) {                                         \
        float v = arr[i];                                                 \
        _Pragma("unroll")                                                 \
        for (int o = 16; o; o >>= 1) v += __shfl_xor_sync(0xffffffffu, v, o); \
        if (lane == 0) red[off + i][wid] = v;                             \
    }
    WREDUCE(g12, 16, 0)
    WREDUCE(g11, 10, 16)
    WREDUCE(g22, 10, 26)
    WREDUCE(sw,   8, 36)
    WREDUCE(ad,   8, 44)
#undef WREDUCE
    __syncthreads();
    if (tid < 52) {
        float t = 0.f;
#pragma unroll
        for (int w = 0; w < 8; w++) t += red[tid][w];
        fin[tid] = t;
    }
    __syncthreads();

    if (tid == 0) {
        const float ab = attn_b[0];
        float sc[8], mx = -1e30f;
#pragma unroll
        for (int w = 0; w < 8; w++) { sc[w] = fin[44 + w] + ab; mx = fmaxf(mx, sc[w]); }
        float s = 0.f;
#pragma unroll
        for (int w = 0; w < 8; w++) { sc[w] = expf(sc[w] - mx); s += sc[w]; }
        const float inv = 1.f / s;
#pragma unroll
        for (int w = 0; w < 8; w++) aprob[w] = sc[w] * inv;
    }

    if (tid < 128) {
        float cw[4];
#pragma unroll
        for (int w = 0; w < 4; w++) cw[w] = cos_w[tid * 4 + w];
        const float cb = cos_b[tid];
        float d12 = 0.f, q1 = 0.f, q2 = 0.f, cs1 = 0.f, cs2 = 0.f;
#pragma unroll
        for (int i = 0; i < 4; i++)
#pragma unroll
            for (int j = 0; j < 4; j++)
                d12 += cw[i] * cw[j] * fin[i * 4 + j];
#pragma unroll
        for (int i = 0; i < 4; i++)
#pragma unroll
            for (int j = i; j < 4; j++) {
                const int t = i * (7 - i) / 2 + j;
                const float c2 = cw[i] * cw[j] * ((i == j) ? 1.f : 2.f);
                q1 += c2 * fin[16 + t];
                q2 += c2 * fin[26 + t];
            }
#pragma unroll
        for (int w = 0; w < 4; w++) {
            cs1 += cw[w] * fin[36 + w];
            cs2 += cw[w] * fin[40 + w];
        }
        d12 += cb * (cs1 + cs2) + (float)DIN * cb * cb;
        q1  += 2.f * cb * cs1 + (float)DIN * cb * cb;
        q2  += 2.f * cb * cs2 + (float)DIN * cb * cb;
        const float n1 = fmaxf(sqrtf(q1), 1e-8f);
        const float n2 = fmaxf(sqrtf(q2), 1e-8f);
        outbuf[(size_t)m * DMODEL + 512 + tid] = d12 / (n1 * n2);
    }
    __syncthreads();

    float a[8];
#pragma unroll
    for (int w = 0; w < 8; w++) a[w] = aprob[w];
    for (int d = tid; d < DIN; d += 256) {
        float p = 0.f;
#pragma unroll
        for (int w = 0; w < 8; w++) p += a[w] * xs[w * DIN + d];
        pooled[(size_t)m * DIN + d] = p;
    }
}

// ---------------------------------------------------------------------------
// tf32 tensor-core GEMM. BM=64 fixed, template BN. BK=32, double-buffered.
//  - B read from packed fragment-order gmem: linear conflict-free STS.128,
//    conflict-free LDS.64 fragment reads.
//  - A staged m-major with ASTRIDE=36: conflict-free STS.128 + LDS.32 frags.
//  - CONV: virtual K' = 3*Kreal; tap = k/2^klog2 shifts A rows within batch.
//  - flags bit0 = relu.
// ---------------------------------------------------------------------------
template<int BN, bool CONV>
__global__ __launch_bounds__(256, 3) void gemm_tc(
    const float* __restrict__ A, int lda,
    const float* __restrict__ Bp,
    const float* __restrict__ bias,
    float* __restrict__ C, int ldc,
    int N, int K, int klog2, int flags)
{
    constexpr int BM  = 64;
    constexpr int NTB = BN / 8;     // n-tiles per block
    constexpr int NT  = NTB / 4;    // n-tiles per warp (4 n-warps)
    constexpr int A4  = BM / 32;    // 2 float4 A-loads / thread / stage
    constexpr int B4  = BN / 32;    // float4 B-loads / thread / stage
    constexpr int ASZ = BM * ASTRIDE;
    constexpr int BSZ = BN * 32;

    extern __shared__ float sm[];
    float* Asm = sm;                 // 2 stages of ASZ
    float* Bsm = sm + 2 * ASZ;       // 2 stages of BSZ

    const int tid  = threadIdx.x;
    const int lane = tid & 31;
    const int w    = tid >> 5;
    const int bm   = blockIdx.y * BM;
    const int bn   = blockIdx.x * BN;
    const int mtw  = (w >> 2) * 2;        // first m-tile (2 per warp)
    const int ntw  = (w & 3) * NT;        // first n-tile
    const int g    = lane >> 2, tg = lane & 3;
    const int ntiles = N >> 3;

    float acc[2][NT][4];
#pragma unroll
    for (int i = 0; i < 2; i++)
#pragma unroll
        for (int j = 0; j < NT; j++)
#pragma unroll
            for (int r = 0; r < 4; r++) acc[i][j][r] = 0.f;

    float4 ra[A4];
    float4 rb[B4];
    const int kmask = CONV ? ((1 << klog2) - 1) : 0;

    auto loadA = [&](int k0) {
        const int t   = CONV ? (k0 >> klog2) : 0;
        const int kr0 = CONV ? (k0 & kmask) : k0;
#pragma unroll
        for (int r = 0; r < A4; r++) {
            const int idx = tid + r * 256;
            const int mm  = idx >> 3, cg = (idx & 7) << 2;
            const int gm  = bm + mm;
            float4 v = make_float4(0.f, 0.f, 0.f, 0.f);
            if (!CONV) {
                v = *reinterpret_cast<const float4*>(A + (size_t)gm * lda + kr0 + cg);
            } else if ((unsigned)((gm & (NB - 1)) + t - 1) < (unsigned)NB) {
                v = *reinterpret_cast<const float4*>(A + (size_t)(gm + t - 1) * lda + kr0 + cg);
            }
            ra[r] = v;
        }
    };
    auto storeA = [&](int st) {
        float* as = Asm + st * ASZ;
#pragma unroll
        for (int r = 0; r < A4; r++) {
            const int idx = tid + r * 256;
            const int mm  = idx >> 3, cg = (idx & 7) << 2;
            float4 v = ra[r];
            v.x = to_tf32(v.x); v.y = to_tf32(v.y);
            v.z = to_tf32(v.z); v.w = to_tf32(v.w);
            *reinterpret_cast<float4*>(&as[mm * ASTRIDE + cg]) = v;
        }
    };
    auto loadB = [&](int k0) {
        const int kt0 = k0 >> 3;
#pragma unroll
        for (int r = 0; r < B4; r++) {
            const int idx   = tid + r * 256;
            const int kbIdx = idx / (2 * BN);
            const int wi    = idx - kbIdx * 2 * BN;
            rb[r] = *reinterpret_cast<const float4*>(
                Bp + (((size_t)(kt0 + kbIdx) * ntiles + (bn >> 3)) << 6) + (wi << 2));
        }
    };
    auto storeB = [&](int st) {
        float* bs = Bsm + st * BSZ;
#pragma unroll
        for (int r = 0; r < B4; r++) {
            const int idx = tid + r * 256;
            *reinterpret_cast<float4*>(&bs[idx << 2]) = rb[r];
        }
    };

    loadA(0); loadB(0);
    storeA(0); storeB(0);
    __syncthreads();

    int st = 0;
    for (int k0 = 0; k0 < K; k0 += 32) {
        const bool more = (k0 + 32) < K;
        if (more) { loadA(k0 + 32); loadB(k0 + 32); }

        const float* as = Asm + st * ASZ;
        const float* bs = Bsm + st * BSZ;
#pragma unroll
        for (int kb = 0; kb < 4; kb++) {
            const int kcol = kb * 8;
            float a[2][4];
#pragma unroll
            for (int mi = 0; mi < 2; mi++) {
                const int m0 = ((mtw + mi) * 16 + g) * ASTRIDE + kcol + tg;
                a[mi][0] = as[m0];
                a[mi][1] = as[m0 + 8 * ASTRIDE];
                a[mi][2] = as[m0 + 4];
                a[mi][3] = as[m0 + 8 * ASTRIDE + 4];
            }
            float2 bf[NT];
#pragma unroll
            for (int nj = 0; nj < NT; nj++)
                bf[nj] = *reinterpret_cast<const float2*>(
                    &bs[(kb * NTB + ntw + nj) * 64 + lane * 2]);
#pragma unroll
            for (int mi = 0; mi < 2; mi++)
#pragma unroll
                for (int nj = 0; nj < NT; nj++)
                    asm volatile(
                        "mma.sync.aligned.m16n8k8.row.col.f32.tf32.tf32.f32 "
                        "{%0,%1,%2,%3}, {%4,%5,%6,%7}, {%8,%9}, {%0,%1,%2,%3};\n"
                        : "+f"(acc[mi][nj][0]), "+f"(acc[mi][nj][1]),
                          "+f"(acc[mi][nj][2]), "+f"(acc[mi][nj][3])
                        : "r"(__float_as_uint(a[mi][0])), "r"(__float_as_uint(a[mi][1])),
                          "r"(__float_as_uint(a[mi][2])), "r"(__float_as_uint(a[mi][3])),
                          "r"(__float_as_uint(bf[nj].x)), "r"(__float_as_uint(bf[nj].y)));
        }

        if (more) {
            storeA(st ^ 1); storeB(st ^ 1);
            __syncthreads();
            st ^= 1;
        }
    }

    // epilogue: c0=[g][2tg], c1=[g][2tg+1], c2=[g+8][2tg], c3=[g+8][2tg+1]
#pragma unroll
    for (int mi = 0; mi < 2; mi++) {
        const int r0 = bm + (mtw + mi) * 16 + g;
#pragma unroll
        for (int nj = 0; nj < NT; nj++) {
            const int c0 = bn + (ntw + nj) * 8 + tg * 2;
#pragma unroll
            for (int hh = 0; hh < 2; hh++) {
                float* crow = C + (size_t)(r0 + hh * 8) * ldc;
#pragma unroll
                for (int cc = 0; cc < 2; cc++) {
                    float v = acc[mi][nj][hh * 2 + cc];
                    if (bias) v += bias[c0 + cc];
                    if (flags & 1) v = fmaxf(v, 0.f);
                    crow[c0 + cc] = v;
                }
            }
        }
    }
}

// ---------------------------------------------------------------------------
// Banded local attention (|i-j|<=1), one warp per (token, head), d_head=80.
// ---------------------------------------------------------------------------
__global__ __launch_bounds__(256) void banded_attn_kernel(
    const float* __restrict__ qkv, float* __restrict__ ctx)
{
    const int gw   = (blockIdx.x * 256 + threadIdx.x) >> 5;
    const int lane = threadIdx.x & 31;
    if (gw >= MROWS * 8) return;
    const int m = gw >> 3;
    const int h = gw & 7;
    const int n = m & (NB - 1);
    const float scale = 0.11180339887498949f;

    const float* qp = qkv + (size_t)m * QKVN + h * 80;
    const float qv0 = qp[lane], qv1 = qp[lane + 32];
    const float qv2 = (lane < 16) ? qp[lane + 64] : 0.f;

    float s[3];
    bool  val[3];
#pragma unroll
    for (int j = 0; j < 3; j++) {
        const int nn = n + j - 1;
        val[j] = (nn >= 0 && nn < NB);
        float acc = 0.f;
        if (val[j]) {
            const float* kp = qkv + (size_t)(m + j - 1) * QKVN + DMODEL + h * 80;
            acc = qv0 * kp[lane] + qv1 * kp[lane + 32];
            if (lane < 16) acc += qv2 * kp[lane + 64];
        }
#pragma unroll
        for (int o = 16; o; o >>= 1) acc += __shfl_xor_sync(0xffffffffu, acc, o);
        s[j] = val[j] ? acc * scale : -1e30f;
    }

    const float mx = fmaxf(s[0], fmaxf(s[1], s[2]));
    float e[3], sum = 0.f;
#pragma unroll
    for (int j = 0; j < 3; j++) {
        e[j] = val[j] ? expf(s[j] - mx) : 0.f;
        sum += e[j];
    }
    const float inv = 1.f / sum;

    float o0 = 0.f, o1 = 0.f, o2 = 0.f;
#pragma unroll
    for (int j = 0; j < 3; j++) {
        if (!val[j]) continue;
        const float p = e[j] * inv;
        const float* vp = qkv + (size_t)(m + j - 1) * QKVN + 2 * DMODEL + h * 80;
        o0 += p * vp[lane];
        o1 += p * vp[lane + 32];
        if (lane < 16) o2 += p * vp[lane + 64];
    }
    float* cp = ctx + (size_t)m * DMODEL + h * 80;
    cp[lane] = o0;
    cp[lane + 32] = o1;
    if (lane < 16) cp[lane + 64] = o2;
}

// ---------------------------------------------------------------------------
__global__ __launch_bounds__(256) void residual_ln_kernel(
    float* __restrict__ out, const float* __restrict__ add,
    const float* __restrict__ g, const float* __restrict__ b)
{
    const int m = blockIdx.x;
    const int tid = threadIdx.x;
    const int lane = tid & 31, wid = tid >> 5;
    __shared__ float red[8];
    __shared__ float mean_s, rstd_s;

    float v[3];
    float s = 0.f;
#pragma unroll
    for (int i = 0; i < 3; i++) {
        const int d = tid + i * 256;
        float t = 0.f;
        if (d < DMODEL) t = out[(size_t)m * DMODEL + d] + add[(size_t)m * DMODEL + d];
        v[i] = t;
        s += t;
    }
#pragma unroll
    for (int o = 16; o; o >>= 1) s += __shfl_xor_sync(0xffffffffu, s, o);
    if (lane == 0) red[wid] = s;
    __syncthreads();
    if (tid == 0) {
        float t = 0.f;
#pragma unroll
        for (int w = 0; w < 8; w++) t += red[w];
        mean_s = t / (float)DMODEL;
    }
    __syncthreads();
    const float mean = mean_s;

    float vs = 0.f;
#pragma unroll
    for (int i = 0; i < 3; i++) {
        const int d = tid + i * 256;
        if (d < DMODEL) { const float dd = v[i] - mean; vs += dd * dd; }
    }
#pragma unroll
    for (int o = 16; o; o >>= 1) vs += __shfl_xor_sync(0xffffffffu, vs, o);
    __syncthreads();
    if (lane == 0) red[wid] = vs;
    __syncthreads();
    if (tid == 0) {
        float t = 0.f;
#pragma unroll
        for (int w = 0; w < 8; w++) t += red[w];
        rstd_s = rsqrtf(t / (float)DMODEL + 1e-5f);
    }
    __syncthreads();
    const float rstd = rstd_s;
#pragma unroll
    for (int i = 0; i < 3; i++) {
        const int d = tid + i * 256;
        if (d < DMODEL)
            out[(size_t)m * DMODEL + d] = (v[i] - mean) * rstd * g[d] + b[d];
    }
}

// ---------------------------------------------------------------------------
__global__ __launch_bounds__(256) void cls_kernel(
    const float* __restrict__ h, const float* __restrict__ w,
    const float* __restrict__ b, float* __restrict__ out)
{
    const int gw   = (blockIdx.x * 256 + threadIdx.x) >> 5;
    const int lane = threadIdx.x & 31;
    if (gw >= MROWS) return;
    float a0 = 0.f, a1 = 0.f;
#pragma unroll
    for (int i = 0; i < 8; i++) {
        const int k = lane + i * 32;
        const float hv = h[(size_t)gw * 256 + k];
        a0 += hv * w[k * 2];
        a1 += hv * w[k * 2 + 1];
    }
#pragma unroll
    for (int o = 16; o; o >>= 1) {
        a0 += __shfl_xor_sync(0xffffffffu, a0, o);
        a1 += __shfl_xor_sync(0xffffffffu, a1, o);
    }
    if (lane == 0) {
        out[(size_t)gw * 2]     = a0 + b[0];
        out[(size_t)gw * 2 + 1] = a1 + b[1];
    }
}

// ---------------------------------------------------------------------------
extern "C" void kernel_launch(void* const* d_in, const int* in_sizes, int n_in,
                              void* d_out, int out_size)
{
    const float* x       = (const float*)d_in[0];
    const float* cos_w   = (const float*)d_in[2];
    const float* cos_b   = (const float*)d_in[3];
    const float* attn_w  = (const float*)d_in[4];
    const float* attn_b  = (const float*)d_in[5];
    const float* conv1_w = (const float*)d_in[6];
    const float* conv1_b = (const float*)d_in[7];
    const float* conv2_w = (const float*)d_in[8];
    const float* conv2_b = (const float*)d_in[9];
    const float* Wq      = (const float*)d_in[10];
    const float* Wk      = (const float*)d_in[11];
    const float* Wv      = (const float*)d_in[12];
    const float* Wo      = (const float*)d_in[13];
    const float* ln1_g   = (const float*)d_in[14];
    const float* ln1_b   = (const float*)d_in[15];
    const float* ff1_w   = (const float*)d_in[16];
    const float* ff1_b   = (const float*)d_in[17];
    const float* ff2_w   = (const float*)d_in[18];
    const float* ff2_b   = (const float*)d_in[19];
    const float* ln2_g   = (const float*)d_in[20];
    const float* ln2_b   = (const float*)d_in[21];
    const float* fc_w    = (const float*)d_in[22];
    const float* fc_b    = (const float*)d_in[23];
    const float* cls_w   = (const float*)d_in[24];
    const float* cls_b   = (const float*)d_in[25];
    float* logits = (float*)d_out;

    float *pooled, *obuf, *qkvb, *ctxb, *tmpb, *ffb, *hb;
    float *wqkv, *wo, *wf1, *wf2, *wfc, *wc1, *wc2;
    cudaGetSymbolAddress((void**)&pooled, g_pooled);
    cudaGetSymbolAddress((void**)&obuf,   g_out);
    cudaGetSymbolAddress((void**)&qkvb,   g_qkv);
    cudaGetSymbolAddress((void**)&ctxb,   g_ctx);
    cudaGetSymbolAddress((void**)&tmpb,   g_tmp);
    cudaGetSymbolAddress((void**)&ffb,    g_ff);
    cudaGetSymbolAddress((void**)&hb,     g_h);
    cudaGetSymbolAddress((void**)&wqkv,   g_wqkv);
    cudaGetSymbolAddress((void**)&wo,     g_wo);
    cudaGetSymbolAddress((void**)&wf1,    g_wf1);
    cudaGetSymbolAddress((void**)&wf2,    g_wf2);
    cudaGetSymbolAddress((void**)&wfc,    g_wfc);
    cudaGetSymbolAddress((void**)&wc1,    g_wc1);
    cudaGetSymbolAddress((void**)&wc2,    g_wc2);

    // dynamic smem sizes (2 stages of A[64*36] + B[BN*32] floats)
    const int smem128 = 2 * (64 * ASTRIDE + 128 * 32) * 4;   // 51200
    const int smem64  = 2 * (64 * ASTRIDE + 64 * 32) * 4;    // 34816

    // idempotent, capture-safe, no static guards
    cudaFuncSetAttribute(pool_sim_kernel,
                         cudaFuncAttributeMaxDynamicSharedMemorySize, 65536);
    cudaFuncSetAttribute(gemm_tc<128, false>,
                         cudaFuncAttributeMaxDynamicSharedMemorySize, smem128);
    cudaFuncSetAttribute(gemm_tc<64, false>,
                         cudaFuncAttributeMaxDynamicSharedMemorySize, smem64);
    cudaFuncSetAttribute(gemm_tc<64, true>,
                         cudaFuncAttributeMaxDynamicSharedMemorySize, smem64);

    // 0. pack all weights into fragment order
    pack_qkv_kernel<<<(NLAYER * DMODEL * QKVN + 255) / 256, 256>>>(Wq, Wk, Wv, wqkv);
    pack_frag_kernel<<<(NLAYER * DMODEL * DMODEL + 255) / 256, 256>>>(Wo, wo, DMODEL, DMODEL, NLAYER);
    pack_frag_kernel<<<(NLAYER * DMODEL * 128 + 255) / 256, 256>>>(ff1_w, wf1, DMODEL, 128, NLAYER);
    pack_frag_kernel<<<(NLAYER * 128 * DMODEL + 255) / 256, 256>>>(ff2_w, wf2, 128, DMODEL, NLAYER);
    pack_frag_kernel<<<(DMODEL * 256 + 255) / 256, 256>>>(fc_w, wfc, DMODEL, 256, 1);
    pack_conv_kernel<<<(256 * DIN * 3 + 255) / 256, 256>>>(conv1_w, wc1, DIN, 256);
    pack_conv_kernel<<<(256 * 256 * 3 + 255) / 256, 256>>>(conv2_w, wc2, 256, 256);

    // 1. pooling + cos-sim
    pool_sim_kernel<<<MROWS, 256, 65536>>>(x, cos_w, cos_b, attn_w, attn_b,
                                           pooled, obuf);

    // 2. conv1: K' = 3*2048 = 6144
    gemm_tc<64, true><<<dim3(4, 64), 256, smem64>>>(
        pooled, DIN, wc1, conv1_b, obuf, DMODEL, 256, 3 * DIN, 11, 1);

    // 3. conv2: K' = 3*256 = 768
    gemm_tc<64, true><<<dim3(4, 64), 256, smem64>>>(
        obuf, DMODEL, wc2, conv2_b, obuf + 256, DMODEL, 256, 3 * 256, 8, 1);

    // 4. transformer layers
    for (int l = 0; l < NLAYER; l++) {
        gemm_tc<128, false><<<dim3(15, 64), 256, smem128>>>(
            obuf, DMODEL, wqkv + (size_t)l * DMODEL * QKVN,
            nullptr, qkvb, QKVN, QKVN, DMODEL, 0, 0);

        banded_attn_kernel<<<MROWS, 256>>>(qkvb, ctxb);

        gemm_tc<128, false><<<dim3(5, 64), 256, smem128>>>(
            ctxb, DMODEL, wo + (size_t)l * DMODEL * DMODEL,
            nullptr, tmpb, DMODEL, DMODEL, DMODEL, 0, 0);
        residual_ln_kernel<<<MROWS, 256>>>(obuf, tmpb,
                                           ln1_g + l * DMODEL, ln1_b + l * DMODEL);

        gemm_tc<64, false><<<dim3(2, 64), 256, smem64>>>(
            obuf, DMODEL, wf1 + (size_t)l * DMODEL * 128,
            ff1_b + l * 128, ffb, 128, 128, DMODEL, 0, 1);
        gemm_tc<128, false><<<dim3(5, 64), 256, smem128>>>(
            ffb, 128, wf2 + (size_t)l * 128 * DMODEL,
            ff2_b + l * DMODEL, tmpb, DMODEL, DMODEL, 128, 0, 0);
        residual_ln_kernel<<<MROWS, 256>>>(obuf, tmpb,
                                           ln2_g + l * DMODEL, ln2_b + l * DMODEL);
    }

    // 5. head
    gemm_tc<64, false><<<dim3(4, 64), 256, smem64>>>(
        obuf, DMODEL, wfc, fc_b, hb, 256, 256, DMODEL, 0, 1);
    cls_kernel<<<(MROWS * 32 + 255) / 256, 256>>>(hb, cls_w, cls_b, logits);
}

// round 12
// speedup vs baseline: 5.9103x; 1.1521x over previous
#include <cuda_runtime.h>
#include <cmath>
#include <cstdint>

// ---------------------------------------------------------------------------
// SceneSegCNNTRM round 11: 3-stage cp.async GEMM pipeline.
//  - B pre-packed (tf32, fragment order) in gmem -> cp.async, zero staging
//  - A cp.async with XOR bank swizzle; tf32 cvt at fragment read
//  - conv taps folded into K (A-shift via cp.async src-size zero-fill)
// ---------------------------------------------------------------------------

#define MROWS   4096
#define NB      1024
#define DIN     2048
#define DMODEL  640
#define NLAYER  6
#define QKVN    1920

__device__ __align__(256) float g_pooled[MROWS * DIN];
__device__ __align__(256) float g_out   [MROWS * DMODEL];
__device__ __align__(256) float g_qkv   [MROWS * QKVN];
__device__ __align__(256) float g_ctx   [MROWS * DMODEL];
__device__ __align__(256) float g_tmp   [MROWS * DMODEL];
__device__ __align__(256) float g_ff    [MROWS * 128];
__device__ __align__(256) float g_h     [MROWS * 256];
// packed (fragment-ordered, tf32-rounded) weights
__device__ __align__(256) float g_wqkv[NLAYER * DMODEL * QKVN];
__device__ __align__(256) float g_wo  [NLAYER * DMODEL * DMODEL];
__device__ __align__(256) float g_wf1 [NLAYER * DMODEL * 128];
__device__ __align__(256) float g_wf2 [NLAYER * 128 * DMODEL];
__device__ __align__(256) float g_wfc [DMODEL * 256];
__device__ __align__(256) float g_wc1 [3 * DIN * 256];
__device__ __align__(256) float g_wc2 [3 * 256 * 256];

__device__ __forceinline__ float to_tf32(float x) {
    asm("cvt.rna.tf32.f32 %0, %0;" : "+f"(x));
    return x;
}

// fragment-order index for B[k][n] in a [K x N] matrix
__device__ __forceinline__ size_t fidx(int k, int n, int N) {
    return ((size_t)(k >> 3) * (N >> 3) + (n >> 3)) * 64
         + (size_t)(((n & 7) * 4 + (k & 3)) * 2 + ((k >> 2) & 1));
}

// 16B cp.async with zero-fill predicate (src-size = 0 -> zeros)
__device__ __forceinline__ void cp16(uint32_t dst, const float* src, bool ok) {
    const int sz = ok ? 16 : 0;
    asm volatile("cp.async.cg.shared.global [%0], [%1], 16, %2;\n"
                 :: "r"(dst), "l"(src), "r"(sz));
}
__device__ __forceinline__ void cp_commit() {
    asm volatile("cp.async.commit_group;\n");
}
__device__ __forceinline__ void cp_wait1() {
    asm volatile("cp.async.wait_group 1;\n");
}

// ---------------------------------------------------------------------------
// weight pack kernels
// ---------------------------------------------------------------------------
__global__ __launch_bounds__(256) void pack_frag_kernel(
    const float* __restrict__ W, float* __restrict__ out, int K, int N, int L)
{
    const int i = blockIdx.x * 256 + threadIdx.x;
    if (i >= L * K * N) return;
    const int l = i / (K * N);
    const int rem = i - l * K * N;
    const int k = rem / N, n = rem - (rem / N) * N;
    out[(size_t)l * K * N + fidx(k, n, N)] = to_tf32(W[i]);
}

__global__ __launch_bounds__(256) void pack_qkv_kernel(
    const float* __restrict__ Wq, const float* __restrict__ Wk,
    const float* __restrict__ Wv, float* __restrict__ out)
{
    const int i = blockIdx.x * 256 + threadIdx.x;
    if (i >= NLAYER * DMODEL * QKVN) return;
    const int l = i / (DMODEL * QKVN);
    const int rem = i - l * DMODEL * QKVN;
    const int k = rem / QKVN, np = rem - k * QKVN;
    const float* W = (np < DMODEL) ? Wq : (np < 2 * DMODEL) ? Wk : Wv;
    const float v = W[(size_t)l * DMODEL * DMODEL + (size_t)k * DMODEL + (np % DMODEL)];
    out[(size_t)l * DMODEL * QKVN + fidx(k, np, QKVN)] = to_tf32(v);
}

__global__ __launch_bounds__(256) void pack_conv_kernel(
    const float* __restrict__ W, float* __restrict__ out, int K, int N)
{
    const int i = blockIdx.x * 256 + threadIdx.x;
    if (i >= N * K * 3) return;
    const int n = i / (K * 3);
    const int r = i - n * K * 3;
    const int k = r / 3, t = r - k * 3;
    out[fidx(t * K + k, n, N)] = to_tf32(W[i]);
}

// ---------------------------------------------------------------------------
// pool + cos-sim (unchanged; correct since R2)
// ---------------------------------------------------------------------------
__global__ __launch_bounds__(256) void pool_sim_kernel(
    const float* __restrict__ x,
    const float* __restrict__ cos_w, const float* __restrict__ cos_b,
    const float* __restrict__ attn_w, const float* __restrict__ attn_b,
    float* __restrict__ pooled, float* __restrict__ outbuf)
{
    extern __shared__ float xs[];   // [8][2048]
    const int m   = blockIdx.x;
    const int tid = threadIdx.x;
    const float* xr = x + (size_t)m * 8 * DIN;

#pragma unroll
    for (int r = 0; r < 16; r++) {
        const int idx = tid + r * 256;
        *reinterpret_cast<float4*>(xs + idx * 4) =
            *reinterpret_cast<const float4*>(xr + idx * 4);
    }
    __syncthreads();

    float g12[16], g11[10], g22[10], sw[8], ad[8];
#pragma unroll
    for (int i = 0; i < 16; i++) g12[i] = 0.f;
#pragma unroll
    for (int i = 0; i < 10; i++) { g11[i] = 0.f; g22[i] = 0.f; }
#pragma unroll
    for (int i = 0; i < 8; i++)  { sw[i] = 0.f; ad[i] = 0.f; }

    for (int d = tid; d < DIN; d += 256) {
        float xv[8];
#pragma unroll
        for (int w = 0; w < 8; w++) xv[w] = xs[w * DIN + d];
        const float aw = attn_w[d];
#pragma unroll
        for (int w = 0; w < 8; w++) { sw[w] += xv[w]; ad[w] += xv[w] * aw; }
#pragma unroll
        for (int i = 0; i < 4; i++)
#pragma unroll
            for (int j = 0; j < 4; j++)
                g12[i * 4 + j] += xv[i] * xv[4 + j];
#pragma unroll
        for (int i = 0; i < 4; i++)
#pragma unroll
            for (int j = i; j < 4; j++) {
                const int t = i * (7 - i) / 2 + j;
                g11[t] += xv[i] * xv[j];
                g22[t] += xv[4 + i] * xv[4 + j];
            }
    }

    __shared__ float red[52][8];
    __shared__ float fin[52];
    __shared__ float aprob[8];
    const int lane = tid & 31, wid = tid >> 5;

#define WREDUCE(arr, n, off)                                              \
    _Pragma("unroll")                                                     \
    for (int i = 0; i < n; i++) {                                         \
        float v = arr[i];                                                 \
        _Pragma("unroll")                                                 \
        for (int o = 16; o; o >>= 1) v += __shfl_xor_sync(0xffffffffu, v, o); \
        if (lane == 0) red[off + i][wid] = v;                             \
    }
    WREDUCE(g12, 16, 0)
    WREDUCE(g11, 10, 16)
    WREDUCE(g22, 10, 26)
    WREDUCE(sw,   8, 36)
    WREDUCE(ad,   8, 44)
#undef WREDUCE
    __syncthreads();
    if (tid < 52) {
        float t = 0.f;
#pragma unroll
        for (int w = 0; w < 8; w++) t += red[tid][w];
        fin[tid] = t;
    }
    __syncthreads();

    if (tid == 0) {
        const float ab = attn_b[0];
        float sc[8], mx = -1e30f;
#pragma unroll
        for (int w = 0; w < 8; w++) { sc[w] = fin[44 + w] + ab; mx = fmaxf(mx, sc[w]); }
        float s = 0.f;
#pragma unroll
        for (int w = 0; w < 8; w++) { sc[w] = expf(sc[w] - mx); s += sc[w]; }
        const float inv = 1.f / s;
#pragma unroll
        for (int w = 0; w < 8; w++) aprob[w] = sc[w] * inv;
    }

    if (tid < 128) {
        float cw[4];
#pragma unroll
        for (int w = 0; w < 4; w++) cw[w] = cos_w[tid * 4 + w];
        const float cb = cos_b[tid];
        float d12 = 0.f, q1 = 0.f, q2 = 0.f, cs1 = 0.f, cs2 = 0.f;
#pragma unroll
        for (int i = 0; i < 4; i++)
#pragma unroll
            for (int j = 0; j < 4; j++)
                d12 += cw[i] * cw[j] * fin[i * 4 + j];
#pragma unroll
        for (int i = 0; i < 4; i++)
#pragma unroll
            for (int j = i; j < 4; j++) {
                const int t = i * (7 - i) / 2 + j;
                const float c2 = cw[i] * cw[j] * ((i == j) ? 1.f : 2.f);
                q1 += c2 * fin[16 + t];
                q2 += c2 * fin[26 + t];
            }
#pragma unroll
        for (int w = 0; w < 4; w++) {
            cs1 += cw[w] * fin[36 + w];
            cs2 += cw[w] * fin[40 + w];
        }
        d12 += cb * (cs1 + cs2) + (float)DIN * cb * cb;
        q1  += 2.f * cb * cs1 + (float)DIN * cb * cb;
        q2  += 2.f * cb * cs2 + (float)DIN * cb * cb;
        const float n1 = fmaxf(sqrtf(q1), 1e-8f);
        const float n2 = fmaxf(sqrtf(q2), 1e-8f);
        outbuf[(size_t)m * DMODEL + 512 + tid] = d12 / (n1 * n2);
    }
    __syncthreads();

    float a[8];
#pragma unroll
    for (int w = 0; w < 8; w++) a[w] = aprob[w];
    for (int d = tid; d < DIN; d += 256) {
        float p = 0.f;
#pragma unroll
        for (int w = 0; w < 8; w++) p += a[w] * xs[w * DIN + d];
        pooled[(size_t)m * DIN + d] = p;
    }
}

// ---------------------------------------------------------------------------
// tf32 tensor-core GEMM. BM=64, template BN, BK=32, 3-stage cp.async.
//  - A: cp.async, XOR swizzle (c ^= 4*(m&7)) -> conflict-free; tf32 cvt at read
//  - B: cp.async of packed fragment-order gmem (pre-converted); linear smem
//  - CONV: virtual K' = 3*Kreal; tap shifts A rows; invalid rows zero-filled
//  - flags bit0 = relu
// ---------------------------------------------------------------------------
template<int BN, bool CONV>
__global__ __launch_bounds__(256, 3) void gemm_tc(
    const float* __restrict__ A, int lda,
    const float* __restrict__ Bp,
    const float* __restrict__ bias,
    float* __restrict__ C, int ldc,
    int N, int K, int klog2, int flags)
{
    constexpr int BM  = 64;
    constexpr int NTB = BN / 8;
    constexpr int NT  = NTB / 4;
    constexpr int A4  = BM / 32;        // 2 cp.async(A)/thread/stage
    constexpr int B4  = BN / 32;        // cp.async(B)/thread/stage
    constexpr int ASZ = BM * 32;        // floats per A stage (swizzled, no pad)
    constexpr int BSZ = BN * 32;        // floats per B stage

    extern __shared__ float sm[];
    float* Asm = sm;                    // 3 stages
    float* Bsm = sm + 3 * ASZ;

    const uint32_t a_smem = (uint32_t)__cvta_generic_to_shared(Asm);
    const uint32_t b_smem = (uint32_t)__cvta_generic_to_shared(Bsm);

    const int tid  = threadIdx.x;
    const int lane = tid & 31;
    const int w    = tid >> 5;
    const int bm   = blockIdx.y * BM;
    const int bn   = blockIdx.x * BN;
    const int mtw  = (w >> 2) * 2;
    const int ntw  = (w & 3) * NT;
    const int g    = lane >> 2, tg = lane & 3;
    const int ntiles = N >> 3;
    const int kmask = CONV ? ((1 << klog2) - 1) : 0;

    float acc[2][NT][4];
#pragma unroll
    for (int i = 0; i < 2; i++)
#pragma unroll
        for (int j = 0; j < NT; j++)
#pragma unroll
            for (int r = 0; r < 4; r++) acc[i][j][r] = 0.f;

    auto issue = [&](int st, int k0) {
        const int t   = CONV ? (k0 >> klog2) : 0;
        const int kr0 = CONV ? (k0 & kmask) : k0;
        const uint32_t as = a_smem + (uint32_t)(st * ASZ * 4);
#pragma unroll
        for (int r = 0; r < A4; r++) {
            const int idx = tid + r * 256;
            const int mm  = idx >> 3, cg = (idx & 7) << 2;
            const int gm  = bm + mm;
            const int swc = cg ^ ((mm & 7) << 2);
            bool ok = true;
            const float* src;
            if (CONV) {
                ok  = ((unsigned)((gm & (NB - 1)) + t - 1) < (unsigned)NB);
                src = ok ? (A + (size_t)(gm + t - 1) * lda + kr0 + cg) : A;
            } else {
                src = A + (size_t)gm * lda + kr0 + cg;
            }
            cp16(as + (uint32_t)((mm * 32 + swc) * 4), src, ok);
        }
        const int kt0 = k0 >> 3;
        const uint32_t bs = b_smem + (uint32_t)(st * BSZ * 4);
#pragma unroll
        for (int r = 0; r < B4; r++) {
            const int idx   = tid + r * 256;
            const int kbIdx = idx / (2 * BN);
            const int wi    = idx - kbIdx * 2 * BN;
            const float* src = Bp
                + (((size_t)(kt0 + kbIdx) * ntiles + (bn >> 3)) << 6) + (wi << 2);
            cp16(bs + (uint32_t)(idx << 4), src, true);
        }
    };

    const int kiters = K >> 5;
    issue(0, 0);
    cp_commit();
    if (kiters > 1) issue(1, 32);
    cp_commit();

    for (int i = 0; i < kiters; i++) {
        cp_wait1();
        __syncthreads();
        const int inext = i + 2;
        if (inext < kiters) {
            int stn = inext - (inext / 3) * 3;
            issue(stn, inext * 32);
        }
        cp_commit();

        const int st = i - (i / 3) * 3;
        const float* as = Asm + st * ASZ;
        const float* bs = Bsm + st * BSZ;
        const int sx = g << 2;
#pragma unroll
        for (int kb = 0; kb < 4; kb++) {
            const int kcol = kb * 8;
            const int c0 = (kcol + tg) ^ sx;
            const int c4 = (kcol + tg + 4) ^ sx;
            float a[2][4];
#pragma unroll
            for (int mi = 0; mi < 2; mi++) {
                const int r0 = ((mtw + mi) * 16 + g) * 32;
                a[mi][0] = to_tf32(as[r0 + c0]);
                a[mi][1] = to_tf32(as[r0 + 256 + c0]);   // +8 rows
                a[mi][2] = to_tf32(as[r0 + c4]);
                a[mi][3] = to_tf32(as[r0 + 256 + c4]);
            }
            float2 bf[NT];
#pragma unroll
            for (int nj = 0; nj < NT; nj++)
                bf[nj] = *reinterpret_cast<const float2*>(
                    &bs[(kb * NTB + ntw + nj) * 64 + lane * 2]);
#pragma unroll
            for (int mi = 0; mi < 2; mi++)
#pragma unroll
                for (int nj = 0; nj < NT; nj++)
                    asm volatile(
                        "mma.sync.aligned.m16n8k8.row.col.f32.tf32.tf32.f32 "
                        "{%0,%1,%2,%3}, {%4,%5,%6,%7}, {%8,%9}, {%0,%1,%2,%3};\n"
                        : "+f"(acc[mi][nj][0]), "+f"(acc[mi][nj][1]),
                          "+f"(acc[mi][nj][2]), "+f"(acc[mi][nj][3])
                        : "r"(__float_as_uint(a[mi][0])), "r"(__float_as_uint(a[mi][1])),
                          "r"(__float_as_uint(a[mi][2])), "r"(__float_as_uint(a[mi][3])),
                          "r"(__float_as_uint(bf[nj].x)), "r"(__float_as_uint(bf[nj].y)));
        }
    }

    // epilogue
#pragma unroll
    for (int mi = 0; mi < 2; mi++) {
        const int r0 = bm + (mtw + mi) * 16 + g;
#pragma unroll
        for (int nj = 0; nj < NT; nj++) {
            const int c0 = bn + (ntw + nj) * 8 + tg * 2;
#pragma unroll
            for (int hh = 0; hh < 2; hh++) {
                float* crow = C + (size_t)(r0 + hh * 8) * ldc;
#pragma unroll
                for (int cc = 0; cc < 2; cc++) {
                    float v = acc[mi][nj][hh * 2 + cc];
                    if (bias) v += bias[c0 + cc];
                    if (flags & 1) v = fmaxf(v, 0.f);
                    crow[c0 + cc] = v;
                }
            }
        }
    }
}

// ---------------------------------------------------------------------------
// Banded local attention (|i-j|<=1), one warp per (token, head), d_head=80.
// ---------------------------------------------------------------------------
__global__ __launch_bounds__(256) void banded_attn_kernel(
    const float* __restrict__ qkv, float* __restrict__ ctx)
{
    const int gw   = (blockIdx.x * 256 + threadIdx.x) >> 5;
    const int lane = threadIdx.x & 31;
    if (gw >= MROWS * 8) return;
    const int m = gw >> 3;
    const int h = gw & 7;
    const int n = m & (NB - 1);
    const float scale = 0.11180339887498949f;

    const float* qp = qkv + (size_t)m * QKVN + h * 80;
    const float qv0 = qp[lane], qv1 = qp[lane + 32];
    const float qv2 = (lane < 16) ? qp[lane + 64] : 0.f;

    float s[3];
    bool  val[3];
#pragma unroll
    for (int j = 0; j < 3; j++) {
        const int nn = n + j - 1;
        val[j] = (nn >= 0 && nn < NB);
        float acc = 0.f;
        if (val[j]) {
            const float* kp = qkv + (size_t)(m + j - 1) * QKVN + DMODEL + h * 80;
            acc = qv0 * kp[lane] + qv1 * kp[lane + 32];
            if (lane < 16) acc += qv2 * kp[lane + 64];
        }
#pragma unroll
        for (int o = 16; o; o >>= 1) acc += __shfl_xor_sync(0xffffffffu, acc, o);
        s[j] = val[j] ? acc * scale : -1e30f;
    }

    const float mx = fmaxf(s[0], fmaxf(s[1], s[2]));
    float e[3], sum = 0.f;
#pragma unroll
    for (int j = 0; j < 3; j++) {
        e[j] = val[j] ? expf(s[j] - mx) : 0.f;
        sum += e[j];
    }
    const float inv = 1.f / sum;

    float o0 = 0.f, o1 = 0.f, o2 = 0.f;
#pragma unroll
    for (int j = 0; j < 3; j++) {
        if (!val[j]) continue;
        const float p = e[j] * inv;
        const float* vp = qkv + (size_t)(m + j - 1) * QKVN + 2 * DMODEL + h * 80;
        o0 += p * vp[lane];
        o1 += p * vp[lane + 32];
        if (lane < 16) o2 += p * vp[lane + 64];
    }
    float* cp = ctx + (size_t)m * DMODEL + h * 80;
    cp[lane] = o0;
    cp[lane + 32] = o1;
    if (lane < 16) cp[lane + 64] = o2;
}

// ---------------------------------------------------------------------------
__global__ __launch_bounds__(256) void residual_ln_kernel(
    float* __restrict__ out, const float* __restrict__ add,
    const float* __restrict__ g, const float* __restrict__ b)
{
    const int m = blockIdx.x;
    const int tid = threadIdx.x;
    const int lane = tid & 31, wid = tid >> 5;
    __shared__ float red[8];
    __shared__ float mean_s, rstd_s;

    float v[3];
    float s = 0.f;
#pragma unroll
    for (int i = 0; i < 3; i++) {
        const int d = tid + i * 256;
        float t = 0.f;
        if (d < DMODEL) t = out[(size_t)m * DMODEL + d] + add[(size_t)m * DMODEL + d];
        v[i] = t;
        s += t;
    }
#pragma unroll
    for (int o = 16; o; o >>= 1) s += __shfl_xor_sync(0xffffffffu, s, o);
    if (lane == 0) red[wid] = s;
    __syncthreads();
    if (tid == 0) {
        float t = 0.f;
#pragma unroll
        for (int w = 0; w < 8; w++) t += red[w];
        mean_s = t / (float)DMODEL;
    }
    __syncthreads();
    const float mean = mean_s;

    float vs = 0.f;
#pragma unroll
    for (int i = 0; i < 3; i++) {
        const int d = tid + i * 256;
        if (d < DMODEL) { const float dd = v[i] - mean; vs += dd * dd; }
    }
#pragma unroll
    for (int o = 16; o; o >>= 1) vs += __shfl_xor_sync(0xffffffffu, vs, o);
    __syncthreads();
    if (lane == 0) red[wid] = vs;
    __syncthreads();
    if (tid == 0) {
        float t = 0.f;
#pragma unroll
        for (int w = 0; w < 8; w++) t += red[w];
        rstd_s = rsqrtf(t / (float)DMODEL + 1e-5f);
    }
    __syncthreads();
    const float rstd = rstd_s;
#pragma unroll
    for (int i = 0; i < 3; i++) {
        const int d = tid + i * 256;
        if (d < DMODEL)
            out[(size_t)m * DMODEL + d] = (v[i] - mean) * rstd * g[d] + b[d];
    }
}

// ---------------------------------------------------------------------------
__global__ __launch_bounds__(256) void cls_kernel(
    const float* __restrict__ h, const float* __restrict__ w,
    const float* __restrict__ b, float* __restrict__ out)
{
    const int gw   = (blockIdx.x * 256 + threadIdx.x) >> 5;
    const int lane = threadIdx.x & 31;
    if (gw >= MROWS) return;
    float a0 = 0.f, a1 = 0.f;
#pragma unroll
    for (int i = 0; i < 8; i++) {
        const int k = lane + i * 32;
        const float hv = h[(size_t)gw * 256 + k];
        a0 += hv * w[k * 2];
        a1 += hv * w[k * 2 + 1];
    }
#pragma unroll
    for (int o = 16; o; o >>= 1) {
        a0 += __shfl_xor_sync(0xffffffffu, a0, o);
        a1 += __shfl_xor_sync(0xffffffffu, a1, o);
    }
    if (lane == 0) {
        out[(size_t)gw * 2]     = a0 + b[0];
        out[(size_t)gw * 2 + 1] = a1 + b[1];
    }
}

// ---------------------------------------------------------------------------
extern "C" void kernel_launch(void* const* d_in, const int* in_sizes, int n_in,
                              void* d_out, int out_size)
{
    const float* x       = (const float*)d_in[0];
    const float* cos_w   = (const float*)d_in[2];
    const float* cos_b   = (const float*)d_in[3];
    const float* attn_w  = (const float*)d_in[4];
    const float* attn_b  = (const float*)d_in[5];
    const float* conv1_w = (const float*)d_in[6];
    const float* conv1_b = (const float*)d_in[7];
    const float* conv2_w = (const float*)d_in[8];
    const float* conv2_b = (const float*)d_in[9];
    const float* Wq      = (const float*)d_in[10];
    const float* Wk      = (const float*)d_in[11];
    const float* Wv      = (const float*)d_in[12];
    const float* Wo      = (const float*)d_in[13];
    const float* ln1_g   = (const float*)d_in[14];
    const float* ln1_b   = (const float*)d_in[15];
    const float* ff1_w   = (const float*)d_in[16];
    const float* ff1_b   = (const float*)d_in[17];
    const float* ff2_w   = (const float*)d_in[18];
    const float* ff2_b   = (const float*)d_in[19];
    const float* ln2_g   = (const float*)d_in[20];
    const float* ln2_b   = (const float*)d_in[21];
    const float* fc_w    = (const float*)d_in[22];
    const float* fc_b    = (const float*)d_in[23];
    const float* cls_w   = (const float*)d_in[24];
    const float* cls_b   = (const float*)d_in[25];
    float* logits = (float*)d_out;

    float *pooled, *obuf, *qkvb, *ctxb, *tmpb, *ffb, *hb;
    float *wqkv, *wo, *wf1, *wf2, *wfc, *wc1, *wc2;
    cudaGetSymbolAddress((void**)&pooled, g_pooled);
    cudaGetSymbolAddress((void**)&obuf,   g_out);
    cudaGetSymbolAddress((void**)&qkvb,   g_qkv);
    cudaGetSymbolAddress((void**)&ctxb,   g_ctx);
    cudaGetSymbolAddress((void**)&tmpb,   g_tmp);
    cudaGetSymbolAddress((void**)&ffb,    g_ff);
    cudaGetSymbolAddress((void**)&hb,     g_h);
    cudaGetSymbolAddress((void**)&wqkv,   g_wqkv);
    cudaGetSymbolAddress((void**)&wo,     g_wo);
    cudaGetSymbolAddress((void**)&wf1,    g_wf1);
    cudaGetSymbolAddress((void**)&wf2,    g_wf2);
    cudaGetSymbolAddress((void**)&wfc,    g_wfc);
    cudaGetSymbolAddress((void**)&wc1,    g_wc1);
    cudaGetSymbolAddress((void**)&wc2,    g_wc2);

    // dynamic smem: 3 stages of (A 64*32 + B BN*32) floats
    const int smem128 = 3 * (64 * 32 + 128 * 32) * 4;   // 73728
    const int smem64  = 3 * (64 * 32 + 64 * 32) * 4;    // 49152

    // idempotent, capture-safe, no static guards
    cudaFuncSetAttribute(pool_sim_kernel,
                         cudaFuncAttributeMaxDynamicSharedMemorySize, 65536);
    cudaFuncSetAttribute(gemm_tc<128, false>,
                         cudaFuncAttributeMaxDynamicSharedMemorySize, smem128);
    cudaFuncSetAttribute(gemm_tc<64, false>,
                         cudaFuncAttributeMaxDynamicSharedMemorySize, smem64);
    cudaFuncSetAttribute(gemm_tc<64, true>,
                         cudaFuncAttributeMaxDynamicSharedMemorySize, smem64);

    // 0. pack all weights into fragment order (tf32-rounded)
    pack_qkv_kernel<<<(NLAYER * DMODEL * QKVN + 255) / 256, 256>>>(Wq, Wk, Wv, wqkv);
    pack_frag_kernel<<<(NLAYER * DMODEL * DMODEL + 255) / 256, 256>>>(Wo, wo, DMODEL, DMODEL, NLAYER);
    pack_frag_kernel<<<(NLAYER * DMODEL * 128 + 255) / 256, 256>>>(ff1_w, wf1, DMODEL, 128, NLAYER);
    pack_frag_kernel<<<(NLAYER * 128 * DMODEL + 255) / 256, 256>>>(ff2_w, wf2, 128, DMODEL, NLAYER);
    pack_frag_kernel<<<(DMODEL * 256 + 255) / 256, 256>>>(fc_w, wfc, DMODEL, 256, 1);
    pack_conv_kernel<<<(256 * DIN * 3 + 255) / 256, 256>>>(conv1_w, wc1, DIN, 256);
    pack_conv_kernel<<<(256 * 256 * 3 + 255) / 256, 256>>>(conv2_w, wc2, 256, 256);

    // 1. pooling + cos-sim
    pool_sim_kernel<<<MROWS, 256, 65536>>>(x, cos_w, cos_b, attn_w, attn_b,
                                           pooled, obuf);

    // 2. conv1: K' = 3*2048 = 6144
    gemm_tc<64, true><<<dim3(4, 64), 256, smem64>>>(
        pooled, DIN, wc1, conv1_b, obuf, DMODEL, 256, 3 * DIN, 11, 1);

    // 3. conv2: K' = 3*256 = 768
    gemm_tc<64, true><<<dim3(4, 64), 256, smem64>>>(
        obuf, DMODEL, wc2, conv2_b, obuf + 256, DMODEL, 256, 3 * 256, 8, 1);

    // 4. transformer layers
    for (int l = 0; l < NLAYER; l++) {
        gemm_tc<128, false><<<dim3(15, 64), 256, smem128>>>(
            obuf, DMODEL, wqkv + (size_t)l * DMODEL * QKVN,
            nullptr, qkvb, QKVN, QKVN, DMODEL, 0, 0);

        banded_attn_kernel<<<MROWS, 256>>>(qkvb, ctxb);

        gemm_tc<128, false><<<dim3(5, 64), 256, smem128>>>(
            ctxb, DMODEL, wo + (size_t)l * DMODEL * DMODEL,
            nullptr, tmpb, DMODEL, DMODEL, DMODEL, 0, 0);
        residual_ln_kernel<<<MROWS, 256>>>(obuf, tmpb,
                                           ln1_g + l * DMODEL, ln1_b + l * DMODEL);

        gemm_tc<64, false><<<dim3(2, 64), 256, smem64>>>(
            obuf, DMODEL, wf1 + (size_t)l * DMODEL * 128,
            ff1_b + l * 128, ffb, 128, 128, DMODEL, 0, 1);
        gemm_tc<128, false><<<dim3(5, 64), 256, smem128>>>(
            ffb, 128, wf2 + (size_t)l * 128 * DMODEL,
            ff2_b + l * DMODEL, tmpb, DMODEL, DMODEL, 128, 0, 0);
        residual_ln_kernel<<<MROWS, 256>>>(obuf, tmpb,
                                           ln2_g + l * DMODEL, ln2_b + l * DMODEL);
    }

    // 5. head
    gemm_tc<64, false><<<dim3(4, 64), 256, smem64>>>(
        obuf, DMODEL, wfc, fc_b, hb, 256, 256, DMODEL, 0, 1);
    cls_kernel<<<(MROWS * 32 + 255) / 256, 256>>>(hb, cls_w, cls_b, logits);
}

// round 13
// speedup vs baseline: 6.2181x; 1.0521x over previous
#include <cuda_runtime.h>
#include <cmath>
#include <cstdint>

// ---------------------------------------------------------------------------
// SceneSegCNNTRM round 12: BM=128 QKV tile, warp-per-row LN, merged packs.
// ---------------------------------------------------------------------------

#define MROWS   4096
#define NB      1024
#define DIN     2048
#define DMODEL  640
#define NLAYER  6
#define QKVN    1920

__device__ __align__(256) float g_pooled[MROWS * DIN];
__device__ __align__(256) float g_out   [MROWS * DMODEL];
__device__ __align__(256) float g_qkv   [MROWS * QKVN];
__device__ __align__(256) float g_ctx   [MROWS * DMODEL];
__device__ __align__(256) float g_tmp   [MROWS * DMODEL];
__device__ __align__(256) float g_ff    [MROWS * 128];
__device__ __align__(256) float g_h     [MROWS * 256];
// packed (fragment-ordered, tf32-rounded) weights
__device__ __align__(256) float g_wqkv[NLAYER * DMODEL * QKVN];
__device__ __align__(256) float g_wo  [NLAYER * DMODEL * DMODEL];
__device__ __align__(256) float g_wf1 [NLAYER * DMODEL * 128];
__device__ __align__(256) float g_wf2 [NLAYER * 128 * DMODEL];
__device__ __align__(256) float g_wfc [DMODEL * 256];
__device__ __align__(256) float g_wc1 [3 * DIN * 256];
__device__ __align__(256) float g_wc2 [3 * 256 * 256];

__device__ __forceinline__ float to_tf32(float x) {
    asm("cvt.rna.tf32.f32 %0, %0;" : "+f"(x));
    return x;
}

// fragment-order index for B[k][n] in a [K x N] matrix
__device__ __forceinline__ size_t fidx(int k, int n, int N) {
    return ((size_t)(k >> 3) * (N >> 3) + (n >> 3)) * 64
         + (size_t)(((n & 7) * 4 + (k & 3)) * 2 + ((k >> 2) & 1));
}

__device__ __forceinline__ void cp16(uint32_t dst, const float* src, bool ok) {
    const int sz = ok ? 16 : 0;
    asm volatile("cp.async.cg.shared.global [%0], [%1], 16, %2;\n"
                 :: "r"(dst), "l"(src), "r"(sz));
}
__device__ __forceinline__ void cp_commit() {
    asm volatile("cp.async.commit_group;\n");
}
__device__ __forceinline__ void cp_wait1() {
    asm volatile("cp.async.wait_group 1;\n");
}

// ---------------------------------------------------------------------------
// merged pack kernels (2 launches total)
// ---------------------------------------------------------------------------
#define SZ_QKV (NLAYER * DMODEL * QKVN)       // 7372800
#define SZ_WO  (NLAYER * DMODEL * DMODEL)     // 2457600
#define SZ_FF1 (NLAYER * DMODEL * 128)        // 491520
#define SZ_FF2 (NLAYER * 128 * DMODEL)        // 491520
#define SZ_FC  (DMODEL * 256)                 // 163840
#define SZ_LIN (SZ_QKV + SZ_WO + SZ_FF1 + SZ_FF2 + SZ_FC)

__global__ __launch_bounds__(256) void pack_linear_kernel(
    const float* __restrict__ Wq, const float* __restrict__ Wk,
    const float* __restrict__ Wv, const float* __restrict__ Wo,
    const float* __restrict__ F1, const float* __restrict__ F2,
    const float* __restrict__ FC,
    float* __restrict__ wqkv, float* __restrict__ wo,
    float* __restrict__ wf1, float* __restrict__ wf2, float* __restrict__ wfc)
{
    int i = blockIdx.x * 256 + threadIdx.x;
    if (i < SZ_QKV) {
        const int l = i / (DMODEL * QKVN);
        const int rem = i - l * DMODEL * QKVN;
        const int k = rem / QKVN, np = rem - k * QKVN;
        const float* W = (np < DMODEL) ? Wq : (np < 2 * DMODEL) ? Wk : Wv;
        const float v = W[(size_t)l * DMODEL * DMODEL + (size_t)k * DMODEL + (np % DMODEL)];
        wqkv[(size_t)l * DMODEL * QKVN + fidx(k, np, QKVN)] = to_tf32(v);
        return;
    }
    i -= SZ_QKV;
    if (i < SZ_WO) {
        const int l = i / (DMODEL * DMODEL);
        const int rem = i - l * DMODEL * DMODEL;
        const int k = rem / DMODEL, n = rem - k * DMODEL;
        wo[(size_t)l * DMODEL * DMODEL + fidx(k, n, DMODEL)] = to_tf32(Wo[i]);
        return;
    }
    i -= SZ_WO;
    if (i < SZ_FF1) {
        const int l = i / (DMODEL * 128);
        const int rem = i - l * DMODEL * 128;
        const int k = rem / 128, n = rem - k * 128;
        wf1[(size_t)l * DMODEL * 128 + fidx(k, n, 128)] = to_tf32(F1[i]);
        return;
    }
    i -= SZ_FF1;
    if (i < SZ_FF2) {
        const int l = i / (128 * DMODEL);
        const int rem = i - l * 128 * DMODEL;
        const int k = rem / DMODEL, n = rem - k * DMODEL;
        wf2[(size_t)l * 128 * DMODEL + fidx(k, n, DMODEL)] = to_tf32(F2[i]);
        return;
    }
    i -= SZ_FF2;
    if (i < SZ_FC) {
        const int k = i / 256, n = i - k * 256;
        wfc[fidx(k, n, 256)] = to_tf32(FC[i]);
    }
}

__global__ __launch_bounds__(256) void pack_conv_kernel(
    const float* __restrict__ W1, const float* __restrict__ W2,
    float* __restrict__ wc1, float* __restrict__ wc2)
{
    int i = blockIdx.x * 256 + threadIdx.x;
    if (i < 3 * DIN * 256) {               // conv1: (Cout=256, Cin=2048, 3)
        const int n = i / (DIN * 3);
        const int r = i - n * (DIN * 3);
        const int k = r / 3, t = r - k * 3;
        wc1[fidx(t * DIN + k, n, 256)] = to_tf32(W1[i]);
        return;
    }
    i -= 3 * DIN * 256;
    if (i < 3 * 256 * 256) {               // conv2: (256, 256, 3)
        const int n = i / (256 * 3);
        const int r = i - n * (256 * 3);
        const int k = r / 3, t = r - k * 3;
        wc2[fidx(t * 256 + k, n, 256)] = to_tf32(W2[i]);
    }
}

// ---------------------------------------------------------------------------
// pool + cos-sim (unchanged; correct since R2)
// ---------------------------------------------------------------------------
__global__ __launch_bounds__(256) void pool_sim_kernel(
    const float* __restrict__ x,
    const float* __restrict__ cos_w, const float* __restrict__ cos_b,
    const float* __restrict__ attn_w, const float* __restrict__ attn_b,
    float* __restrict__ pooled, float* __restrict__ outbuf)
{
    extern __shared__ float xs[];
    const int m   = blockIdx.x;
    const int tid = threadIdx.x;
    const float* xr = x + (size_t)m * 8 * DIN;

#pragma unroll
    for (int r = 0; r < 16; r++) {
        const int idx = tid + r * 256;
        *reinterpret_cast<float4*>(xs + idx * 4) =
            *reinterpret_cast<const float4*>(xr + idx * 4);
    }
    __syncthreads();

    float g12[16], g11[10], g22[10], sw[8], ad[8];
#pragma unroll
    for (int i = 0; i < 16; i++) g12[i] = 0.f;
#pragma unroll
    for (int i = 0; i < 10; i++) { g11[i] = 0.f; g22[i] = 0.f; }
#pragma unroll
    for (int i = 0; i < 8; i++)  { sw[i] = 0.f; ad[i] = 0.f; }

    for (int d = tid; d < DIN; d += 256) {
        float xv[8];
#pragma unroll
        for (int w = 0; w < 8; w++) xv[w] = xs[w * DIN + d];
        const float aw = attn_w[d];
#pragma unroll
        for (int w = 0; w < 8; w++) { sw[w] += xv[w]; ad[w] += xv[w] * aw; }
#pragma unroll
        for (int i = 0; i < 4; i++)
#pragma unroll
            for (int j = 0; j < 4; j++)
                g12[i * 4 + j] += xv[i] * xv[4 + j];
#pragma unroll
        for (int i = 0; i < 4; i++)
#pragma unroll
            for (int j = i; j < 4; j++) {
                const int t = i * (7 - i) / 2 + j;
                g11[t] += xv[i] * xv[j];
                g22[t] += xv[4 + i] * xv[4 + j];
            }
    }

    __shared__ float red[52][8];
    __shared__ float fin[52];
    __shared__ float aprob[8];
    const int lane = tid & 31, wid = tid >> 5;

#define WREDUCE(arr, n, off)                                              \
    _Pragma("unroll")                                                     \
    for (int i = 0; i < n; i++) {                                         \
        float v = arr[i];                                                 \
        _Pragma("unroll")                                                 \
        for (int o = 16; o; o >>= 1) v += __shfl_xor_sync(0xffffffffu, v, o); \
        if (lane == 0) red[off + i][wid] = v;                             \
    }
    WREDUCE(g12, 16, 0)
    WREDUCE(g11, 10, 16)
    WREDUCE(g22, 10, 26)
    WREDUCE(sw,   8, 36)
    WREDUCE(ad,   8, 44)
#undef WREDUCE
    __syncthreads();
    if (tid < 52) {
        float t = 0.f;
#pragma unroll
        for (int w = 0; w < 8; w++) t += red[tid][w];
        fin[tid] = t;
    }
    __syncthreads();

    if (tid == 0) {
        const float ab = attn_b[0];
        float sc[8], mx = -1e30f;
#pragma unroll
        for (int w = 0; w < 8; w++) { sc[w] = fin[44 + w] + ab; mx = fmaxf(mx, sc[w]); }
        float s = 0.f;
#pragma unroll
        for (int w = 0; w < 8; w++) { sc[w] = expf(sc[w] - mx); s += sc[w]; }
        const float inv = 1.f / s;
#pragma unroll
        for (int w = 0; w < 8; w++) aprob[w] = sc[w] * inv;
    }

    if (tid < 128) {
        float cw[4];
#pragma unroll
        for (int w = 0; w < 4; w++) cw[w] = cos_w[tid * 4 + w];
        const float cb = cos_b[tid];
        float d12 = 0.f, q1 = 0.f, q2 = 0.f, cs1 = 0.f, cs2 = 0.f;
#pragma unroll
        for (int i = 0; i < 4; i++)
#pragma unroll
            for (int j = 0; j < 4; j++)
                d12 += cw[i] * cw[j] * fin[i * 4 + j];
#pragma unroll
        for (int i = 0; i < 4; i++)
#pragma unroll
            for (int j = i; j < 4; j++) {
                const int t = i * (7 - i) / 2 + j;
                const float c2 = cw[i] * cw[j] * ((i == j) ? 1.f : 2.f);
                q1 += c2 * fin[16 + t];
                q2 += c2 * fin[26 + t];
            }
#pragma unroll
        for (int w = 0; w < 4; w++) {
            cs1 += cw[w] * fin[36 + w];
            cs2 += cw[w] * fin[40 + w];
        }
        d12 += cb * (cs1 + cs2) + (float)DIN * cb * cb;
        q1  += 2.f * cb * cs1 + (float)DIN * cb * cb;
        q2  += 2.f * cb * cs2 + (float)DIN * cb * cb;
        const float n1 = fmaxf(sqrtf(q1), 1e-8f);
        const float n2 = fmaxf(sqrtf(q2), 1e-8f);
        outbuf[(size_t)m * DMODEL + 512 + tid] = d12 / (n1 * n2);
    }
    __syncthreads();

    float a[8];
#pragma unroll
    for (int w = 0; w < 8; w++) a[w] = aprob[w];
    for (int d = tid; d < DIN; d += 256) {
        float p = 0.f;
#pragma unroll
        for (int w = 0; w < 8; w++) p += a[w] * xs[w * DIN + d];
        pooled[(size_t)m * DIN + d] = p;
    }
}

// ---------------------------------------------------------------------------
// tf32 tensor-core GEMM. Template BM (64/128) x BN, BK=32, 3-stage cp.async.
//  - warps: WM = BM/32 m-groups x (8/WM) n-groups; 2 m-tiles/warp
//  - A: cp.async + XOR swizzle; tf32 cvt at fragment read
//  - B: cp.async of packed fragment-order gmem
//  - CONV: virtual K' = 3*Kreal, A rows shifted per tap, zero-filled OOB
// ---------------------------------------------------------------------------
template<int BM, int BN, bool CONV>
__global__ __launch_bounds__(256, (BM == 64 ? 3 : 2)) void gemm_tc(
    const float* __restrict__ A, int lda,
    const float* __restrict__ Bp,
    const float* __restrict__ bias,
    float* __restrict__ C, int ldc,
    int N, int K, int klog2, int flags)
{
    constexpr int NTB = BN / 8;
    constexpr int WNW = 8 / (BM / 32);     // n-warp groups
    constexpr int NT  = NTB / WNW;         // n-tiles per warp
    constexpr int A4  = BM / 32;
    constexpr int B4  = BN / 32;
    constexpr int ASZ = BM * 32;
    constexpr int BSZ = BN * 32;

    extern __shared__ float sm[];
    float* Asm = sm;
    float* Bsm = sm + 3 * ASZ;

    const uint32_t a_smem = (uint32_t)__cvta_generic_to_shared(Asm);
    const uint32_t b_smem = (uint32_t)__cvta_generic_to_shared(Bsm);

    const int tid  = threadIdx.x;
    const int lane = tid & 31;
    const int w    = tid >> 5;
    const int bm   = blockIdx.y * BM;
    const int bn   = blockIdx.x * BN;
    const int mtw  = (w / WNW) * 2;
    const int ntw  = (w % WNW) * NT;
    const int g    = lane >> 2, tg = lane & 3;
    const int ntiles = N >> 3;
    const int kmask = CONV ? ((1 << klog2) - 1) : 0;

    float acc[2][NT][4];
#pragma unroll
    for (int i = 0; i < 2; i++)
#pragma unroll
        for (int j = 0; j < NT; j++)
#pragma unroll
            for (int r = 0; r < 4; r++) acc[i][j][r] = 0.f;

    auto issue = [&](int st, int k0) {
        const int t   = CONV ? (k0 >> klog2) : 0;
        const int kr0 = CONV ? (k0 & kmask) : k0;
        const uint32_t as = a_smem + (uint32_t)(st * ASZ * 4);
#pragma unroll
        for (int r = 0; r < A4; r++) {
            const int idx = tid + r * 256;
            const int mm  = idx >> 3, cg = (idx & 7) << 2;
            const int gm  = bm + mm;
            const int swc = cg ^ ((mm & 7) << 2);
            bool ok = true;
            const float* src;
            if (CONV) {
                ok  = ((unsigned)((gm & (NB - 1)) + t - 1) < (unsigned)NB);
                src = ok ? (A + (size_t)(gm + t - 1) * lda + kr0 + cg) : A;
            } else {
                src = A + (size_t)gm * lda + kr0 + cg;
            }
            cp16(as + (uint32_t)((mm * 32 + swc) * 4), src, ok);
        }
        const int kt0 = k0 >> 3;
        const uint32_t bs = b_smem + (uint32_t)(st * BSZ * 4);
#pragma unroll
        for (int r = 0; r < B4; r++) {
            const int idx   = tid + r * 256;
            const int kbIdx = idx / (2 * BN);
            const int wi    = idx - kbIdx * 2 * BN;
            const float* src = Bp
                + (((size_t)(kt0 + kbIdx) * ntiles + (bn >> 3)) << 6) + (wi << 2);
            cp16(bs + (uint32_t)(idx << 4), src, true);
        }
    };

    const int kiters = K >> 5;
    issue(0, 0);
    cp_commit();
    if (kiters > 1) issue(1, 32);
    cp_commit();

    for (int i = 0; i < kiters; i++) {
        cp_wait1();
        __syncthreads();
        const int inext = i + 2;
        if (inext < kiters) {
            int stn = inext - (inext / 3) * 3;
            issue(stn, inext * 32);
        }
        cp_commit();

        const int st = i - (i / 3) * 3;
        const float* as = Asm + st * ASZ;
        const float* bs = Bsm + st * BSZ;
        const int sx = g << 2;
#pragma unroll
        for (int kb = 0; kb < 4; kb++) {
            const int kcol = kb * 8;
            const int c0 = (kcol + tg) ^ sx;
            const int c4 = (kcol + tg + 4) ^ sx;
            float a[2][4];
#pragma unroll
            for (int mi = 0; mi < 2; mi++) {
                const int r0 = ((mtw + mi) * 16 + g) * 32;
                a[mi][0] = to_tf32(as[r0 + c0]);
                a[mi][1] = to_tf32(as[r0 + 256 + c0]);
                a[mi][2] = to_tf32(as[r0 + c4]);
                a[mi][3] = to_tf32(as[r0 + 256 + c4]);
            }
            float2 bf[NT];
#pragma unroll
            for (int nj = 0; nj < NT; nj++)
                bf[nj] = *reinterpret_cast<const float2*>(
                    &bs[(kb * NTB + ntw + nj) * 64 + lane * 2]);
#pragma unroll
            for (int mi = 0; mi < 2; mi++)
#pragma unroll
                for (int nj = 0; nj < NT; nj++)
                    asm volatile(
                        "mma.sync.aligned.m16n8k8.row.col.f32.tf32.tf32.f32 "
                        "{%0,%1,%2,%3}, {%4,%5,%6,%7}, {%8,%9}, {%0,%1,%2,%3};\n"
                        : "+f"(acc[mi][nj][0]), "+f"(acc[mi][nj][1]),
                          "+f"(acc[mi][nj][2]), "+f"(acc[mi][nj][3])
                        : "r"(__float_as_uint(a[mi][0])), "r"(__float_as_uint(a[mi][1])),
                          "r"(__float_as_uint(a[mi][2])), "r"(__float_as_uint(a[mi][3])),
                          "r"(__float_as_uint(bf[nj].x)), "r"(__float_as_uint(bf[nj].y)));
        }
    }

    // epilogue
#pragma unroll
    for (int mi = 0; mi < 2; mi++) {
        const int r0 = bm + (mtw + mi) * 16 + g;
#pragma unroll
        for (int nj = 0; nj < NT; nj++) {
            const int c0 = bn + (ntw + nj) * 8 + tg * 2;
#pragma unroll
            for (int hh = 0; hh < 2; hh++) {
                float* crow = C + (size_t)(r0 + hh * 8) * ldc;
#pragma unroll
                for (int cc = 0; cc < 2; cc++) {
                    float v = acc[mi][nj][hh * 2 + cc];
                    if (bias) v += bias[c0 + cc];
                    if (flags & 1) v = fmaxf(v, 0.f);
                    crow[c0 + cc] = v;
                }
            }
        }
    }
}

// ---------------------------------------------------------------------------
// Banded local attention (|i-j|<=1), one warp per (token, head), d_head=80.
// ---------------------------------------------------------------------------
__global__ __launch_bounds__(256) void banded_attn_kernel(
    const float* __restrict__ qkv, float* __restrict__ ctx)
{
    const int gw   = (blockIdx.x * 256 + threadIdx.x) >> 5;
    const int lane = threadIdx.x & 31;
    if (gw >= MROWS * 8) return;
    const int m = gw >> 3;
    const int h = gw & 7;
    const int n = m & (NB - 1);
    const float scale = 0.11180339887498949f;

    const float* qp = qkv + (size_t)m * QKVN + h * 80;
    const float qv0 = qp[lane], qv1 = qp[lane + 32];
    const float qv2 = (lane < 16) ? qp[lane + 64] : 0.f;

    float s[3];
    bool  val[3];
#pragma unroll
    for (int j = 0; j < 3; j++) {
        const int nn = n + j - 1;
        val[j] = (nn >= 0 && nn < NB);
        float acc = 0.f;
        if (val[j]) {
            const float* kp = qkv + (size_t)(m + j - 1) * QKVN + DMODEL + h * 80;
            acc = qv0 * kp[lane] + qv1 * kp[lane + 32];
            if (lane < 16) acc += qv2 * kp[lane + 64];
        }
#pragma unroll
        for (int o = 16; o; o >>= 1) acc += __shfl_xor_sync(0xffffffffu, acc, o);
        s[j] = val[j] ? acc * scale : -1e30f;
    }

    const float mx = fmaxf(s[0], fmaxf(s[1], s[2]));
    float e[3], sum = 0.f;
#pragma unroll
    for (int j = 0; j < 3; j++) {
        e[j] = val[j] ? expf(s[j] - mx) : 0.f;
        sum += e[j];
    }
    const float inv = 1.f / sum;

    float o0 = 0.f, o1 = 0.f, o2 = 0.f;
#pragma unroll
    for (int j = 0; j < 3; j++) {
        if (!val[j]) continue;
        const float p = e[j] * inv;
        const float* vp = qkv + (size_t)(m + j - 1) * QKVN + 2 * DMODEL + h * 80;
        o0 += p * vp[lane];
        o1 += p * vp[lane + 32];
        if (lane < 16) o2 += p * vp[lane + 64];
    }
    float* cp = ctx + (size_t)m * DMODEL + h * 80;
    cp[lane] = o0;
    cp[lane + 32] = o1;
    if (lane < 16) cp[lane + 64] = o2;
}

// ---------------------------------------------------------------------------
// warp-per-row residual + LayerNorm: out[m] = LN(out[m]+add[m])*g + b
// 8 rows/block, float4 path, shuffle-only reductions.
// ---------------------------------------------------------------------------
__global__ __launch_bounds__(256) void residual_ln_kernel(
    float* __restrict__ out, const float* __restrict__ add,
    const float* __restrict__ g, const float* __restrict__ b)
{
    const int row  = blockIdx.x * 8 + (threadIdx.x >> 5);
    const int lane = threadIdx.x & 31;

    const float4* o4 = reinterpret_cast<const float4*>(out + (size_t)row * DMODEL);
    const float4* a4 = reinterpret_cast<const float4*>(add + (size_t)row * DMODEL);

    float4 v[5];
    float s = 0.f;
#pragma unroll
    for (int i = 0; i < 5; i++) {
        const float4 ov = o4[i * 32 + lane];
        const float4 av = a4[i * 32 + lane];
        v[i] = make_float4(ov.x + av.x, ov.y + av.y, ov.z + av.z, ov.w + av.w);
        s += v[i].x + v[i].y + v[i].z + v[i].w;
    }
#pragma unroll
    for (int o = 16; o; o >>= 1) s += __shfl_xor_sync(0xffffffffu, s, o);
    const float mean = s * (1.f / (float)DMODEL);

    float vs = 0.f;
#pragma unroll
    for (int i = 0; i < 5; i++) {
        const float dx = v[i].x - mean, dy = v[i].y - mean;
        const float dz = v[i].z - mean, dw = v[i].w - mean;
        vs += dx * dx + dy * dy + dz * dz + dw * dw;
    }
#pragma unroll
    for (int o = 16; o; o >>= 1) vs += __shfl_xor_sync(0xffffffffu, vs, o);
    const float rstd = rsqrtf(vs * (1.f / (float)DMODEL) + 1e-5f);

    float4* w4 = reinterpret_cast<float4*>(out + (size_t)row * DMODEL);
    const float4* g4 = reinterpret_cast<const float4*>(g);
    const float4* b4 = reinterpret_cast<const float4*>(b);
#pragma unroll
    for (int i = 0; i < 5; i++) {
        const float4 gv = g4[i * 32 + lane];
        const float4 bv = b4[i * 32 + lane];
        w4[i * 32 + lane] = make_float4(
            (v[i].x - mean) * rstd * gv.x + bv.x,
            (v[i].y - mean) * rstd * gv.y + bv.y,
            (v[i].z - mean) * rstd * gv.z + bv.z,
            (v[i].w - mean) * rstd * gv.w + bv.w);
    }
}

// ---------------------------------------------------------------------------
__global__ __launch_bounds__(256) void cls_kernel(
    const float* __restrict__ h, const float* __restrict__ w,
    const float* __restrict__ b, float* __restrict__ out)
{
    const int gw   = (blockIdx.x * 256 + threadIdx.x) >> 5;
    const int lane = threadIdx.x & 31;
    if (gw >= MROWS) return;
    float a0 = 0.f, a1 = 0.f;
#pragma unroll
    for (int i = 0; i < 8; i++) {
        const int k = lane + i * 32;
        const float hv = h[(size_t)gw * 256 + k];
        a0 += hv * w[k * 2];
        a1 += hv * w[k * 2 + 1];
    }
#pragma unroll
    for (int o = 16; o; o >>= 1) {
        a0 += __shfl_xor_sync(0xffffffffu, a0, o);
        a1 += __shfl_xor_sync(0xffffffffu, a1, o);
    }
    if (lane == 0) {
        out[(size_t)gw * 2]     = a0 + b[0];
        out[(size_t)gw * 2 + 1] = a1 + b[1];
    }
}

// ---------------------------------------------------------------------------
extern "C" void kernel_launch(void* const* d_in, const int* in_sizes, int n_in,
                              void* d_out, int out_size)
{
    const float* x       = (const float*)d_in[0];
    const float* cos_w   = (const float*)d_in[2];
    const float* cos_b   = (const float*)d_in[3];
    const float* attn_w  = (const float*)d_in[4];
    const float* attn_b  = (const float*)d_in[5];
    const float* conv1_w = (const float*)d_in[6];
    const float* conv1_b = (const float*)d_in[7];
    const float* conv2_w = (const float*)d_in[8];
    const float* conv2_b = (const float*)d_in[9];
    const float* Wq      = (const float*)d_in[10];
    const float* Wk      = (const float*)d_in[11];
    const float* Wv      = (const float*)d_in[12];
    const float* Wo      = (const float*)d_in[13];
    const float* ln1_g   = (const float*)d_in[14];
    const float* ln1_b   = (const float*)d_in[15];
    const float* ff1_w   = (const float*)d_in[16];
    const float* ff1_b   = (const float*)d_in[17];
    const float* ff2_w   = (const float*)d_in[18];
    const float* ff2_b   = (const float*)d_in[19];
    const float* ln2_g   = (const float*)d_in[20];
    const float* ln2_b   = (const float*)d_in[21];
    const float* fc_w    = (const float*)d_in[22];
    const float* fc_b    = (const float*)d_in[23];
    const float* cls_w   = (const float*)d_in[24];
    const float* cls_b   = (const float*)d_in[25];
    float* logits = (float*)d_out;

    float *pooled, *obuf, *qkvb, *ctxb, *tmpb, *ffb, *hb;
    float *wqkv, *wo, *wf1, *wf2, *wfc, *wc1, *wc2;
    cudaGetSymbolAddress((void**)&pooled, g_pooled);
    cudaGetSymbolAddress((void**)&obuf,   g_out);
    cudaGetSymbolAddress((void**)&qkvb,   g_qkv);
    cudaGetSymbolAddress((void**)&ctxb,   g_ctx);
    cudaGetSymbolAddress((void**)&tmpb,   g_tmp);
    cudaGetSymbolAddress((void**)&ffb,    g_ff);
    cudaGetSymbolAddress((void**)&hb,     g_h);
    cudaGetSymbolAddress((void**)&wqkv,   g_wqkv);
    cudaGetSymbolAddress((void**)&wo,     g_wo);
    cudaGetSymbolAddress((void**)&wf1,    g_wf1);
    cudaGetSymbolAddress((void**)&wf2,    g_wf2);
    cudaGetSymbolAddress((void**)&wfc,    g_wfc);
    cudaGetSymbolAddress((void**)&wc1,    g_wc1);
    cudaGetSymbolAddress((void**)&wc2,    g_wc2);

    // dynamic smem: 3 stages of (A BM*32 + B BN*32) floats
    const int smemQKV = 3 * (128 * 32 + 128 * 32) * 4;  // 98304
    const int smem128 = 3 * (64 * 32 + 128 * 32) * 4;   // 73728
    const int smem64  = 3 * (64 * 32 + 64 * 32) * 4;    // 49152

    cudaFuncSetAttribute(pool_sim_kernel,
                         cudaFuncAttributeMaxDynamicSharedMemorySize, 65536);
    cudaFuncSetAttribute(gemm_tc<128, 128, false>,
                         cudaFuncAttributeMaxDynamicSharedMemorySize, smemQKV);
    cudaFuncSetAttribute(gemm_tc<64, 128, false>,
                         cudaFuncAttributeMaxDynamicSharedMemorySize, smem128);
    cudaFuncSetAttribute(gemm_tc<64, 64, false>,
                         cudaFuncAttributeMaxDynamicSharedMemorySize, smem64);
    cudaFuncSetAttribute(gemm_tc<64, 64, true>,
                         cudaFuncAttributeMaxDynamicSharedMemorySize, smem64);

    // 0. pack weights (2 launches)
    pack_linear_kernel<<<(SZ_LIN + 255) / 256, 256>>>(
        Wq, Wk, Wv, Wo, ff1_w, ff2_w, fc_w, wqkv, wo, wf1, wf2, wfc);
    pack_conv_kernel<<<(3 * DIN * 256 + 3 * 256 * 256 + 255) / 256, 256>>>(
        conv1_w, conv2_w, wc1, wc2);

    // 1. pooling + cos-sim
    pool_sim_kernel<<<MROWS, 256, 65536>>>(x, cos_w, cos_b, attn_w, attn_b,
                                           pooled, obuf);

    // 2. conv1: K' = 3*2048 = 6144
    gemm_tc<64, 64, true><<<dim3(4, 64), 256, smem64>>>(
        pooled, DIN, wc1, conv1_b, obuf, DMODEL, 256, 3 * DIN, 11, 1);

    // 3. conv2: K' = 3*256 = 768
    gemm_tc<64, 64, true><<<dim3(4, 64), 256, smem64>>>(
        obuf, DMODEL, wc2, conv2_b, obuf + 256, DMODEL, 256, 3 * 256, 8, 1);

    // 4. transformer layers (QKV of layer 0 is launch #6 -> ncu target)
    for (int l = 0; l < NLAYER; l++) {
        gemm_tc<128, 128, false><<<dim3(15, 32), 256, smemQKV>>>(
            obuf, DMODEL, wqkv + (size_t)l * DMODEL * QKVN,
            nullptr, qkvb, QKVN, QKVN, DMODEL, 0, 0);

        banded_attn_kernel<<<MROWS, 256>>>(qkvb, ctxb);

        gemm_tc<64, 128, false><<<dim3(5, 64), 256, smem128>>>(
            ctxb, DMODEL, wo + (size_t)l * DMODEL * DMODEL,
            nullptr, tmpb, DMODEL, DMODEL, DMODEL, 0, 0);
        residual_ln_kernel<<<MROWS / 8, 256>>>(obuf, tmpb,
                                               ln1_g + l * DMODEL, ln1_b + l * DMODEL);

        gemm_tc<64, 64, false><<<dim3(2, 64), 256, smem64>>>(
            obuf, DMODEL, wf1 + (size_t)l * DMODEL * 128,
            ff1_b + l * 128, ffb, 128, 128, DMODEL, 0, 1);
        gemm_tc<64, 128, false><<<dim3(5, 64), 256, smem128>>>(
            ffb, 128, wf2 + (size_t)l * 128 * DMODEL,
            ff2_b + l * DMODEL, tmpb, DMODEL, DMODEL, 128, 0, 0);
        residual_ln_kernel<<<MROWS / 8, 256>>>(obuf, tmpb,
                                               ln2_g + l * DMODEL, ln2_b + l * DMODEL);
    }

    // 5. head
    gemm_tc<64, 64, false><<<dim3(4, 64), 256, smem64>>>(
        obuf, DMODEL, wfc, fc_b, hb, 256, 256, DMODEL, 0, 1);
    cls_kernel<<<(MROWS * 32 + 255) / 256, 256>>>(hb, cls_w, cls_b, logits);
}

// round 14
// speedup vs baseline: 6.6292x; 1.0661x over previous
#include <cuda_runtime.h>
#include <cmath>
#include <cstdint>

// ---------------------------------------------------------------------------
// SceneSegCNNTRM round 13: no A-cvt (HW tf32 truncation), smem-staged banded
// attention, float2 GEMM epilogue. Carries R12's cp.async pipeline + packs.
// ---------------------------------------------------------------------------

#define MROWS   4096
#define NB      1024
#define DIN     2048
#define DMODEL  640
#define NLAYER  6
#define QKVN    1920

__device__ __align__(256) float g_pooled[MROWS * DIN];
__device__ __align__(256) float g_out   [MROWS * DMODEL];
__device__ __align__(256) float g_qkv   [MROWS * QKVN];
__device__ __align__(256) float g_ctx   [MROWS * DMODEL];
__device__ __align__(256) float g_tmp   [MROWS * DMODEL];
__device__ __align__(256) float g_ff    [MROWS * 128];
__device__ __align__(256) float g_h     [MROWS * 256];
// packed (fragment-ordered, tf32-rounded) weights
__device__ __align__(256) float g_wqkv[NLAYER * DMODEL * QKVN];
__device__ __align__(256) float g_wo  [NLAYER * DMODEL * DMODEL];
__device__ __align__(256) float g_wf1 [NLAYER * DMODEL * 128];
__device__ __align__(256) float g_wf2 [NLAYER * 128 * DMODEL];
__device__ __align__(256) float g_wfc [DMODEL * 256];
__device__ __align__(256) float g_wc1 [3 * DIN * 256];
__device__ __align__(256) float g_wc2 [3 * 256 * 256];

__device__ __forceinline__ float to_tf32(float x) {
    asm("cvt.rna.tf32.f32 %0, %0;" : "+f"(x));
    return x;
}

// fragment-order index for B[k][n] in a [K x N] matrix
__device__ __forceinline__ size_t fidx(int k, int n, int N) {
    return ((size_t)(k >> 3) * (N >> 3) + (n >> 3)) * 64
         + (size_t)(((n & 7) * 4 + (k & 3)) * 2 + ((k >> 2) & 1));
}

__device__ __forceinline__ void cp16(uint32_t dst, const float* src, bool ok) {
    const int sz = ok ? 16 : 0;
    asm volatile("cp.async.cg.shared.global [%0], [%1], 16, %2;\n"
                 :: "r"(dst), "l"(src), "r"(sz));
}
__device__ __forceinline__ void cp_commit() {
    asm volatile("cp.async.commit_group;\n");
}
__device__ __forceinline__ void cp_wait1() {
    asm volatile("cp.async.wait_group 1;\n");
}

// ---------------------------------------------------------------------------
// merged pack kernels (2 launches)
// ---------------------------------------------------------------------------
#define SZ_QKV (NLAYER * DMODEL * QKVN)
#define SZ_WO  (NLAYER * DMODEL * DMODEL)
#define SZ_FF1 (NLAYER * DMODEL * 128)
#define SZ_FF2 (NLAYER * 128 * DMODEL)
#define SZ_FC  (DMODEL * 256)
#define SZ_LIN (SZ_QKV + SZ_WO + SZ_FF1 + SZ_FF2 + SZ_FC)

__global__ __launch_bounds__(256) void pack_linear_kernel(
    const float* __restrict__ Wq, const float* __restrict__ Wk,
    const float* __restrict__ Wv, const float* __restrict__ Wo,
    const float* __restrict__ F1, const float* __restrict__ F2,
    const float* __restrict__ FC,
    float* __restrict__ wqkv, float* __restrict__ wo,
    float* __restrict__ wf1, float* __restrict__ wf2, float* __restrict__ wfc)
{
    int i = blockIdx.x * 256 + threadIdx.x;
    if (i < SZ_QKV) {
        const int l = i / (DMODEL * QKVN);
        const int rem = i - l * DMODEL * QKVN;
        const int k = rem / QKVN, np = rem - k * QKVN;
        const float* W = (np < DMODEL) ? Wq : (np < 2 * DMODEL) ? Wk : Wv;
        const float v = W[(size_t)l * DMODEL * DMODEL + (size_t)k * DMODEL + (np % DMODEL)];
        wqkv[(size_t)l * DMODEL * QKVN + fidx(k, np, QKVN)] = to_tf32(v);
        return;
    }
    i -= SZ_QKV;
    if (i < SZ_WO) {
        const int l = i / (DMODEL * DMODEL);
        const int rem = i - l * DMODEL * DMODEL;
        const int k = rem / DMODEL, n = rem - k * DMODEL;
        wo[(size_t)l * DMODEL * DMODEL + fidx(k, n, DMODEL)] = to_tf32(Wo[i]);
        return;
    }
    i -= SZ_WO;
    if (i < SZ_FF1) {
        const int l = i / (DMODEL * 128);
        const int rem = i - l * DMODEL * 128;
        const int k = rem / 128, n = rem - k * 128;
        wf1[(size_t)l * DMODEL * 128 + fidx(k, n, 128)] = to_tf32(F1[i]);
        return;
    }
    i -= SZ_FF1;
    if (i < SZ_FF2) {
        const int l = i / (128 * DMODEL);
        const int rem = i - l * 128 * DMODEL;
        const int k = rem / DMODEL, n = rem - k * DMODEL;
        wf2[(size_t)l * 128 * DMODEL + fidx(k, n, DMODEL)] = to_tf32(F2[i]);
        return;
    }
    i -= SZ_FF2;
    if (i < SZ_FC) {
        const int k = i / 256, n = i - k * 256;
        wfc[fidx(k, n, 256)] = to_tf32(FC[i]);
    }
}

__global__ __launch_bounds__(256) void pack_conv_kernel(
    const float* __restrict__ W1, const float* __restrict__ W2,
    float* __restrict__ wc1, float* __restrict__ wc2)
{
    int i = blockIdx.x * 256 + threadIdx.x;
    if (i < 3 * DIN * 256) {
        const int n = i / (DIN * 3);
        const int r = i - n * (DIN * 3);
        const int k = r / 3, t = r - k * 3;
        wc1[fidx(t * DIN + k, n, 256)] = to_tf32(W1[i]);
        return;
    }
    i -= 3 * DIN * 256;
    if (i < 3 * 256 * 256) {
        const int n = i / (256 * 3);
        const int r = i - n * (256 * 3);
        const int k = r / 3, t = r - k * 3;
        wc2[fidx(t * 256 + k, n, 256)] = to_tf32(W2[i]);
    }
}

// ---------------------------------------------------------------------------
// pool + cos-sim (unchanged; correct since R2)
// ---------------------------------------------------------------------------
__global__ __launch_bounds__(256) void pool_sim_kernel(
    const float* __restrict__ x,
    const float* __restrict__ cos_w, const float* __restrict__ cos_b,
    const float* __restrict__ attn_w, const float* __restrict__ attn_b,
    float* __restrict__ pooled, float* __restrict__ outbuf)
{
    extern __shared__ float xs[];
    const int m   = blockIdx.x;
    const int tid = threadIdx.x;
    const float* xr = x + (size_t)m * 8 * DIN;

#pragma unroll
    for (int r = 0; r < 16; r++) {
        const int idx = tid + r * 256;
        *reinterpret_cast<float4*>(xs + idx * 4) =
            *reinterpret_cast<const float4*>(xr + idx * 4);
    }
    __syncthreads();

    float g12[16], g11[10], g22[10], sw[8], ad[8];
#pragma unroll
    for (int i = 0; i < 16; i++) g12[i] = 0.f;
#pragma unroll
    for (int i = 0; i < 10; i++) { g11[i] = 0.f; g22[i] = 0.f; }
#pragma unroll
    for (int i = 0; i < 8; i++)  { sw[i] = 0.f; ad[i] = 0.f; }

    for (int d = tid; d < DIN; d += 256) {
        float xv[8];
#pragma unroll
        for (int w = 0; w < 8; w++) xv[w] = xs[w * DIN + d];
        const float aw = attn_w[d];
#pragma unroll
        for (int w = 0; w < 8; w++) { sw[w] += xv[w]; ad[w] += xv[w] * aw; }
#pragma unroll
        for (int i = 0; i < 4; i++)
#pragma unroll
            for (int j = 0; j < 4; j++)
                g12[i * 4 + j] += xv[i] * xv[4 + j];
#pragma unroll
        for (int i = 0; i < 4; i++)
#pragma unroll
            for (int j = i; j < 4; j++) {
                const int t = i * (7 - i) / 2 + j;
                g11[t] += xv[i] * xv[j];
                g22[t] += xv[4 + i] * xv[4 + j];
            }
    }

    __shared__ float red[52][8];
    __shared__ float fin[52];
    __shared__ float aprob[8];
    const int lane = tid & 31, wid = tid >> 5;

#define WREDUCE(arr, n, off)                                              \
    _Pragma("unroll")                                                     \
    for (int i = 0; i < n; i++) {                                         \
        float v = arr[i];                                                 \
        _Pragma("unroll")                                                 \
        for (int o = 16; o; o >>= 1) v += __shfl_xor_sync(0xffffffffu, v, o); \
        if (lane == 0) red[off + i][wid] = v;                             \
    }
    WREDUCE(g12, 16, 0)
    WREDUCE(g11, 10, 16)
    WREDUCE(g22, 10, 26)
    WREDUCE(sw,   8, 36)
    WREDUCE(ad,   8, 44)
#undef WREDUCE
    __syncthreads();
    if (tid < 52) {
        float t = 0.f;
#pragma unroll
        for (int w = 0; w < 8; w++) t += red[tid][w];
        fin[tid] = t;
    }
    __syncthreads();

    if (tid == 0) {
        const float ab = attn_b[0];
        float sc[8], mx = -1e30f;
#pragma unroll
        for (int w = 0; w < 8; w++) { sc[w] = fin[44 + w] + ab; mx = fmaxf(mx, sc[w]); }
        float s = 0.f;
#pragma unroll
        for (int w = 0; w < 8; w++) { sc[w] = expf(sc[w] - mx); s += sc[w]; }
        const float inv = 1.f / s;
#pragma unroll
        for (int w = 0; w < 8; w++) aprob[w] = sc[w] * inv;
    }

    if (tid < 128) {
        float cw[4];
#pragma unroll
        for (int w = 0; w < 4; w++) cw[w] = cos_w[tid * 4 + w];
        const float cb = cos_b[tid];
        float d12 = 0.f, q1 = 0.f, q2 = 0.f, cs1 = 0.f, cs2 = 0.f;
#pragma unroll
        for (int i = 0; i < 4; i++)
#pragma unroll
            for (int j = 0; j < 4; j++)
                d12 += cw[i] * cw[j] * fin[i * 4 + j];
#pragma unroll
        for (int i = 0; i < 4; i++)
#pragma unroll
            for (int j = i; j < 4; j++) {
                const int t = i * (7 - i) / 2 + j;
                const float c2 = cw[i] * cw[j] * ((i == j) ? 1.f : 2.f);
                q1 += c2 * fin[16 + t];
                q2 += c2 * fin[26 + t];
            }
#pragma unroll
        for (int w = 0; w < 4; w++) {
            cs1 += cw[w] * fin[36 + w];
            cs2 += cw[w] * fin[40 + w];
        }
        d12 += cb * (cs1 + cs2) + (float)DIN * cb * cb;
        q1  += 2.f * cb * cs1 + (float)DIN * cb * cb;
        q2  += 2.f * cb * cs2 + (float)DIN * cb * cb;
        const float n1 = fmaxf(sqrtf(q1), 1e-8f);
        const float n2 = fmaxf(sqrtf(q2), 1e-8f);
        outbuf[(size_t)m * DMODEL + 512 + tid] = d12 / (n1 * n2);
    }
    __syncthreads();

    float a[8];
#pragma unroll
    for (int w = 0; w < 8; w++) a[w] = aprob[w];
    for (int d = tid; d < DIN; d += 256) {
        float p = 0.f;
#pragma unroll
        for (int w = 0; w < 8; w++) p += a[w] * xs[w * DIN + d];
        pooled[(size_t)m * DIN + d] = p;
    }
}

// ---------------------------------------------------------------------------
// tf32 tensor-core GEMM. BM x BN, BK=32, 3-stage cp.async.
//  - A raw fp32 into mma.tf32 (HW truncation; B pre-rounded at pack)
//  - B cp.async of packed fragment-order gmem
//  - CONV: virtual K' = 3*Kreal, A rows shifted per tap, zero-filled OOB
// ---------------------------------------------------------------------------
template<int BM, int BN, bool CONV>
__global__ __launch_bounds__(256, (BM == 64 ? 3 : 2)) void gemm_tc(
    const float* __restrict__ A, int lda,
    const float* __restrict__ Bp,
    const float* __restrict__ bias,
    float* __restrict__ C, int ldc,
    int N, int K, int klog2, int flags)
{
    constexpr int NTB = BN / 8;
    constexpr int WNW = 8 / (BM / 32);
    constexpr int NT  = NTB / WNW;
    constexpr int A4  = BM / 32;
    constexpr int B4  = BN / 32;
    constexpr int ASZ = BM * 32;
    constexpr int BSZ = BN * 32;

    extern __shared__ float sm[];
    float* Asm = sm;
    float* Bsm = sm + 3 * ASZ;

    const uint32_t a_smem = (uint32_t)__cvta_generic_to_shared(Asm);
    const uint32_t b_smem = (uint32_t)__cvta_generic_to_shared(Bsm);

    const int tid  = threadIdx.x;
    const int lane = tid & 31;
    const int w    = tid >> 5;
    const int bm   = blockIdx.y * BM;
    const int bn   = blockIdx.x * BN;
    const int mtw  = (w / WNW) * 2;
    const int ntw  = (w % WNW) * NT;
    const int g    = lane >> 2, tg = lane & 3;
    const int ntiles = N >> 3;
    const int kmask = CONV ? ((1 << klog2) - 1) : 0;

    float acc[2][NT][4];
#pragma unroll
    for (int i = 0; i < 2; i++)
#pragma unroll
        for (int j = 0; j < NT; j++)
#pragma unroll
            for (int r = 0; r < 4; r++) acc[i][j][r] = 0.f;

    auto issue = [&](int st, int k0) {
        const int t   = CONV ? (k0 >> klog2) : 0;
        const int kr0 = CONV ? (k0 & kmask) : k0;
        const uint32_t as = a_smem + (uint32_t)(st * ASZ * 4);
#pragma unroll
        for (int r = 0; r < A4; r++) {
            const int idx = tid + r * 256;
            const int mm  = idx >> 3, cg = (idx & 7) << 2;
            const int gm  = bm + mm;
            const int swc = cg ^ ((mm & 7) << 2);
            bool ok = true;
            const float* src;
            if (CONV) {
                ok  = ((unsigned)((gm & (NB - 1)) + t - 1) < (unsigned)NB);
                src = ok ? (A + (size_t)(gm + t - 1) * lda + kr0 + cg) : A;
            } else {
                src = A + (size_t)gm * lda + kr0 + cg;
            }
            cp16(as + (uint32_t)((mm * 32 + swc) * 4), src, ok);
        }
        const int kt0 = k0 >> 3;
        const uint32_t bs = b_smem + (uint32_t)(st * BSZ * 4);
#pragma unroll
        for (int r = 0; r < B4; r++) {
            const int idx   = tid + r * 256;
            const int kbIdx = idx / (2 * BN);
            const int wi    = idx - kbIdx * 2 * BN;
            const float* src = Bp
                + (((size_t)(kt0 + kbIdx) * ntiles + (bn >> 3)) << 6) + (wi << 2);
            cp16(bs + (uint32_t)(idx << 4), src, true);
        }
    };

    const int kiters = K >> 5;
    issue(0, 0);
    cp_commit();
    if (kiters > 1) issue(1, 32);
    cp_commit();

    for (int i = 0; i < kiters; i++) {
        cp_wait1();
        __syncthreads();
        const int inext = i + 2;
        if (inext < kiters) {
            int stn = inext - (inext / 3) * 3;
            issue(stn, inext * 32);
        }
        cp_commit();

        const int st = i - (i / 3) * 3;
        const float* as = Asm + st * ASZ;
        const float* bs = Bsm + st * BSZ;
        const int sx = g << 2;
#pragma unroll
        for (int kb = 0; kb < 4; kb++) {
            const int kcol = kb * 8;
            const int c0 = (kcol + tg) ^ sx;
            const int c4 = (kcol + tg + 4) ^ sx;
            float a[2][4];
#pragma unroll
            for (int mi = 0; mi < 2; mi++) {
                const int r0 = ((mtw + mi) * 16 + g) * 32;
                a[mi][0] = as[r0 + c0];          // raw fp32 -> HW tf32 truncation
                a[mi][1] = as[r0 + 256 + c0];
                a[mi][2] = as[r0 + c4];
                a[mi][3] = as[r0 + 256 + c4];
            }
            float2 bf[NT];
#pragma unroll
            for (int nj = 0; nj < NT; nj++)
                bf[nj] = *reinterpret_cast<const float2*>(
                    &bs[(kb * NTB + ntw + nj) * 64 + lane * 2]);
#pragma unroll
            for (int mi = 0; mi < 2; mi++)
#pragma unroll
                for (int nj = 0; nj < NT; nj++)
                    asm volatile(
                        "mma.sync.aligned.m16n8k8.row.col.f32.tf32.tf32.f32 "
                        "{%0,%1,%2,%3}, {%4,%5,%6,%7}, {%8,%9}, {%0,%1,%2,%3};\n"
                        : "+f"(acc[mi][nj][0]), "+f"(acc[mi][nj][1]),
                          "+f"(acc[mi][nj][2]), "+f"(acc[mi][nj][3])
                        : "r"(__float_as_uint(a[mi][0])), "r"(__float_as_uint(a[mi][1])),
                          "r"(__float_as_uint(a[mi][2])), "r"(__float_as_uint(a[mi][3])),
                          "r"(__float_as_uint(bf[nj].x)), "r"(__float_as_uint(bf[nj].y)));
        }
    }

    // epilogue (float2 stores; consecutive cc pairs)
#pragma unroll
    for (int mi = 0; mi < 2; mi++) {
        const int r0 = bm + (mtw + mi) * 16 + g;
#pragma unroll
        for (int nj = 0; nj < NT; nj++) {
            const int c0 = bn + (ntw + nj) * 8 + tg * 2;
            const float bx = bias ? bias[c0]     : 0.f;
            const float by = bias ? bias[c0 + 1] : 0.f;
#pragma unroll
            for (int hh = 0; hh < 2; hh++) {
                float vx = acc[mi][nj][hh * 2]     + bx;
                float vy = acc[mi][nj][hh * 2 + 1] + by;
                if (flags & 1) { vx = fmaxf(vx, 0.f); vy = fmaxf(vy, 0.f); }
                *reinterpret_cast<float2*>(
                    C + (size_t)(r0 + hh * 8) * ldc + c0) = make_float2(vx, vy);
            }
        }
    }
}

// ---------------------------------------------------------------------------
// Banded local attention, smem-staged: one block per token (8 warps = 8 heads).
// Stage q + k[m-1..m+1] + v[m-1..m+1] (7 x 640 floats) coalesced, compute from
// smem. d_head = 80.
// ---------------------------------------------------------------------------
__global__ __launch_bounds__(256) void banded_attn_kernel(
    const float* __restrict__ qkv, float* __restrict__ ctx)
{
    __shared__ float qs[DMODEL];
    __shared__ float ks[3][DMODEL];
    __shared__ float vs[3][DMODEL];

    const int m   = blockIdx.x;
    const int tid = threadIdx.x;
    const int n   = m & (NB - 1);

    // stage: 7 segments x 160 float4
    for (int idx = tid; idx < 7 * 160; idx += 256) {
        const int seg = idx / 160;
        const int off = idx - seg * 160;
        float4 val = make_float4(0.f, 0.f, 0.f, 0.f);
        float* dst;
        if (seg == 0) {
            val = *reinterpret_cast<const float4*>(qkv + (size_t)m * QKVN + off * 4);
            dst = qs + off * 4;
        } else {
            const int j     = (seg - 1) % 3;          // row m-1+j
            const int which = (seg - 1) / 3;          // 0 = k, 1 = v
            const int nn = n + j - 1;
            if ((unsigned)nn < (unsigned)NB)
                val = *reinterpret_cast<const float4*>(
                    qkv + (size_t)(m + j - 1) * QKVN + (which ? 2 * DMODEL : DMODEL) + off * 4);
            dst = (which ? vs[j] : ks[j]) + off * 4;
        }
        *reinterpret_cast<float4*>(dst) = val;
    }
    __syncthreads();

    const int h    = tid >> 5;
    const int lane = tid & 31;
    const float scale = 0.11180339887498949f;   // 1/sqrt(80)
    const int base = h * 80;

    const float qv0 = qs[base + lane];
    const float qv1 = qs[base + lane + 32];
    const float qv2 = (lane < 16) ? qs[base + lane + 64] : 0.f;

    bool val3[3];
    float s[3];
#pragma unroll
    for (int j = 0; j < 3; j++) {
        const int nn = n + j - 1;
        val3[j] = ((unsigned)nn < (unsigned)NB);
        float acc = qv0 * ks[j][base + lane] + qv1 * ks[j][base + lane + 32];
        if (lane < 16) acc += qv2 * ks[j][base + lane + 64];
#pragma unroll
        for (int o = 16; o; o >>= 1) acc += __shfl_xor_sync(0xffffffffu, acc, o);
        s[j] = val3[j] ? acc * scale : -1e30f;
    }

    const float mx = fmaxf(s[0], fmaxf(s[1], s[2]));
    float e[3], sum = 0.f;
#pragma unroll
    for (int j = 0; j < 3; j++) {
        e[j] = val3[j] ? expf(s[j] - mx) : 0.f;
        sum += e[j];
    }
    const float inv = 1.f / sum;

    float o0 = 0.f, o1 = 0.f, o2 = 0.f;
#pragma unroll
    for (int j = 0; j < 3; j++) {
        const float p = e[j] * inv;
        o0 += p * vs[j][base + lane];
        o1 += p * vs[j][base + lane + 32];
        if (lane < 16) o2 += p * vs[j][base + lane + 64];
    }
    float* cp = ctx + (size_t)m * DMODEL + base;
    cp[lane]      = o0;
    cp[lane + 32] = o1;
    if (lane < 16) cp[lane + 64] = o2;
}

// ---------------------------------------------------------------------------
// warp-per-row residual + LayerNorm
// ---------------------------------------------------------------------------
__global__ __launch_bounds__(256) void residual_ln_kernel(
    float* __restrict__ out, const float* __restrict__ add,
    const float* __restrict__ g, const float* __restrict__ b)
{
    const int row  = blockIdx.x * 8 + (threadIdx.x >> 5);
    const int lane = threadIdx.x & 31;

    const float4* o4 = reinterpret_cast<const float4*>(out + (size_t)row * DMODEL);
    const float4* a4 = reinterpret_cast<const float4*>(add + (size_t)row * DMODEL);

    float4 v[5];
    float s = 0.f;
#pragma unroll
    for (int i = 0; i < 5; i++) {
        const float4 ov = o4[i * 32 + lane];
        const float4 av = a4[i * 32 + lane];
        v[i] = make_float4(ov.x + av.x, ov.y + av.y, ov.z + av.z, ov.w + av.w);
        s += v[i].x + v[i].y + v[i].z + v[i].w;
    }
#pragma unroll
    for (int o = 16; o; o >>= 1) s += __shfl_xor_sync(0xffffffffu, s, o);
    const float mean = s * (1.f / (float)DMODEL);

    float vs = 0.f;
#pragma unroll
    for (int i = 0; i < 5; i++) {
        const float dx = v[i].x - mean, dy = v[i].y - mean;
        const float dz = v[i].z - mean, dw = v[i].w - mean;
        vs += dx * dx + dy * dy + dz * dz + dw * dw;
    }
#pragma unroll
    for (int o = 16; o; o >>= 1) vs += __shfl_xor_sync(0xffffffffu, vs, o);
    const float rstd = rsqrtf(vs * (1.f / (float)DMODEL) + 1e-5f);

    float4* w4 = reinterpret_cast<float4*>(out + (size_t)row * DMODEL);
    const float4* g4 = reinterpret_cast<const float4*>(g);
    const float4* b4 = reinterpret_cast<const float4*>(b);
#pragma unroll
    for (int i = 0; i < 5; i++) {
        const float4 gv = g4[i * 32 + lane];
        const float4 bv = b4[i * 32 + lane];
        w4[i * 32 + lane] = make_float4(
            (v[i].x - mean) * rstd * gv.x + bv.x,
            (v[i].y - mean) * rstd * gv.y + bv.y,
            (v[i].z - mean) * rstd * gv.z + bv.z,
            (v[i].w - mean) * rstd * gv.w + bv.w);
    }
}

// ---------------------------------------------------------------------------
__global__ __launch_bounds__(256) void cls_kernel(
    const float* __restrict__ h, const float* __restrict__ w,
    const float* __restrict__ b, float* __restrict__ out)
{
    const int gw   = (blockIdx.x * 256 + threadIdx.x) >> 5;
    const int lane = threadIdx.x & 31;
    if (gw >= MROWS) return;
    float a0 = 0.f, a1 = 0.f;
#pragma unroll
    for (int i = 0; i < 8; i++) {
        const int k = lane + i * 32;
        const float hv = h[(size_t)gw * 256 + k];
        a0 += hv * w[k * 2];
        a1 += hv * w[k * 2 + 1];
    }
#pragma unroll
    for (int o = 16; o; o >>= 1) {
        a0 += __shfl_xor_sync(0xffffffffu, a0, o);
        a1 += __shfl_xor_sync(0xffffffffu, a1, o);
    }
    if (lane == 0) {
        out[(size_t)gw * 2]     = a0 + b[0];
        out[(size_t)gw * 2 + 1] = a1 + b[1];
    }
}

// ---------------------------------------------------------------------------
extern "C" void kernel_launch(void* const* d_in, const int* in_sizes, int n_in,
                              void* d_out, int out_size)
{
    const float* x       = (const float*)d_in[0];
    const float* cos_w   = (const float*)d_in[2];
    const float* cos_b   = (const float*)d_in[3];
    const float* attn_w  = (const float*)d_in[4];
    const float* attn_b  = (const float*)d_in[5];
    const float* conv1_w = (const float*)d_in[6];
    const float* conv1_b = (const float*)d_in[7];
    const float* conv2_w = (const float*)d_in[8];
    const float* conv2_b = (const float*)d_in[9];
    const float* Wq      = (const float*)d_in[10];
    const float* Wk      = (const float*)d_in[11];
    const float* Wv      = (const float*)d_in[12];
    const float* Wo      = (const float*)d_in[13];
    const float* ln1_g   = (const float*)d_in[14];
    const float* ln1_b   = (const float*)d_in[15];
    const float* ff1_w   = (const float*)d_in[16];
    const float* ff1_b   = (const float*)d_in[17];
    const float* ff2_w   = (const float*)d_in[18];
    const float* ff2_b   = (const float*)d_in[19];
    const float* ln2_g   = (const float*)d_in[20];
    const float* ln2_b   = (const float*)d_in[21];
    const float* fc_w    = (const float*)d_in[22];
    const float* fc_b    = (const float*)d_in[23];
    const float* cls_w   = (const float*)d_in[24];
    const float* cls_b   = (const float*)d_in[25];
    float* logits = (float*)d_out;

    float *pooled, *obuf, *qkvb, *ctxb, *tmpb, *ffb, *hb;
    float *wqkv, *wo, *wf1, *wf2, *wfc, *wc1, *wc2;
    cudaGetSymbolAddress((void**)&pooled, g_pooled);
    cudaGetSymbolAddress((void**)&obuf,   g_out);
    cudaGetSymbolAddress((void**)&qkvb,   g_qkv);
    cudaGetSymbolAddress((void**)&ctxb,   g_ctx);
    cudaGetSymbolAddress((void**)&tmpb,   g_tmp);
    cudaGetSymbolAddress((void**)&ffb,    g_ff);
    cudaGetSymbolAddress((void**)&hb,     g_h);
    cudaGetSymbolAddress((void**)&wqkv,   g_wqkv);
    cudaGetSymbolAddress((void**)&wo,     g_wo);
    cudaGetSymbolAddress((void**)&wf1,    g_wf1);
    cudaGetSymbolAddress((void**)&wf2,    g_wf2);
    cudaGetSymbolAddress((void**)&wfc,    g_wfc);
    cudaGetSymbolAddress((void**)&wc1,    g_wc1);
    cudaGetSymbolAddress((void**)&wc2,    g_wc2);

    const int smemQKV = 3 * (128 * 32 + 128 * 32) * 4;  // 98304
    const int smem128 = 3 * (64 * 32 + 128 * 32) * 4;   // 73728
    const int smem64  = 3 * (64 * 32 + 64 * 32) * 4;    // 49152

    cudaFuncSetAttribute(pool_sim_kernel,
                         cudaFuncAttributeMaxDynamicSharedMemorySize, 65536);
    cudaFuncSetAttribute(gemm_tc<128, 128, false>,
                         cudaFuncAttributeMaxDynamicSharedMemorySize, smemQKV);
    cudaFuncSetAttribute(gemm_tc<64, 128, false>,
                         cudaFuncAttributeMaxDynamicSharedMemorySize, smem128);
    cudaFuncSetAttribute(gemm_tc<64, 64, false>,
                         cudaFuncAttributeMaxDynamicSharedMemorySize, smem64);
    cudaFuncSetAttribute(gemm_tc<64, 64, true>,
                         cudaFuncAttributeMaxDynamicSharedMemorySize, smem64);

    // 0. pack weights
    pack_linear_kernel<<<(SZ_LIN + 255) / 256, 256>>>(
        Wq, Wk, Wv, Wo, ff1_w, ff2_w, fc_w, wqkv, wo, wf1, wf2, wfc);
    pack_conv_kernel<<<(3 * DIN * 256 + 3 * 256 * 256 + 255) / 256, 256>>>(
        conv1_w, conv2_w, wc1, wc2);

    // 1. pooling + cos-sim
    pool_sim_kernel<<<MROWS, 256, 65536>>>(x, cos_w, cos_b, attn_w, attn_b,
                                           pooled, obuf);

    // 2. conv1: K' = 6144
    gemm_tc<64, 64, true><<<dim3(4, 64), 256, smem64>>>(
        pooled, DIN, wc1, conv1_b, obuf, DMODEL, 256, 3 * DIN, 11, 1);

    // 3. conv2: K' = 768
    gemm_tc<64, 64, true><<<dim3(4, 64), 256, smem64>>>(
        obuf, DMODEL, wc2, conv2_b, obuf + 256, DMODEL, 256, 3 * 256, 8, 1);

    // 4. transformer layers
    for (int l = 0; l < NLAYER; l++) {
        gemm_tc<128, 128, false><<<dim3(15, 32), 256, smemQKV>>>(
            obuf, DMODEL, wqkv + (size_t)l * DMODEL * QKVN,
            nullptr, qkvb, QKVN, QKVN, DMODEL, 0, 0);

        banded_attn_kernel<<<MROWS, 256>>>(qkvb, ctxb);

        gemm_tc<64, 128, false><<<dim3(5, 64), 256, smem128>>>(
            ctxb, DMODEL, wo + (size_t)l * DMODEL * DMODEL,
            nullptr, tmpb, DMODEL, DMODEL, DMODEL, 0, 0);
        residual_ln_kernel<<<MROWS / 8, 256>>>(obuf, tmpb,
                                               ln1_g + l * DMODEL, ln1_b + l * DMODEL);

        gemm_tc<64, 64, false><<<dim3(2, 64), 256, smem64>>>(
            obuf, DMODEL, wf1 + (size_t)l * DMODEL * 128,
            ff1_b + l * 128, ffb, 128, 128, DMODEL, 0, 1);
        gemm_tc<64, 128, false><<<dim3(5, 64), 256, smem128>>>(
            ffb, 128, wf2 + (size_t)l * 128 * DMODEL,
            ff2_b + l * DMODEL, tmpb, DMODEL, DMODEL, 128, 0, 0);
        residual_ln_kernel<<<MROWS / 8, 256>>>(obuf, tmpb,
                                               ln2_g + l * DMODEL, ln2_b + l * DMODEL);
    }

    // 5. head
    gemm_tc<64, 64, false><<<dim3(4, 64), 256, smem64>>>(
        obuf, DMODEL, wfc, fc_b, hb, 256, 256, DMODEL, 0, 1);
    cls_kernel<<<(MROWS * 32 + 255) / 256, 256>>>(hb, cls_w, cls_b, logits);
}

// round 17
// speedup vs baseline: 6.8111x; 1.0274x over previous
#include <cuda_runtime.h>
#include <cmath>
#include <cstdint>

// ---------------------------------------------------------------------------
// SceneSegCNNTRM round 14: ldmatrix A-fragment loads (8 scalar LDS -> 2 LDSM
// per kb). Carries R13: cp.async pipeline, packed-fragment B, HW tf32 trunc
// on A, smem-staged attention, warp-per-row LN.
// ---------------------------------------------------------------------------

#define MROWS   4096
#define NB      1024
#define DIN     2048
#define DMODEL  640
#define NLAYER  6
#define QKVN    1920

__device__ __align__(256) float g_pooled[MROWS * DIN];
__device__ __align__(256) float g_out   [MROWS * DMODEL];
__device__ __align__(256) float g_qkv   [MROWS * QKVN];
__device__ __align__(256) float g_ctx   [MROWS * DMODEL];
__device__ __align__(256) float g_tmp   [MROWS * DMODEL];
__device__ __align__(256) float g_ff    [MROWS * 128];
__device__ __align__(256) float g_h     [MROWS * 256];
// packed (fragment-ordered, tf32-rounded) weights
__device__ __align__(256) float g_wqkv[NLAYER * DMODEL * QKVN];
__device__ __align__(256) float g_wo  [NLAYER * DMODEL * DMODEL];
__device__ __align__(256) float g_wf1 [NLAYER * DMODEL * 128];
__device__ __align__(256) float g_wf2 [NLAYER * 128 * DMODEL];
__device__ __align__(256) float g_wfc [DMODEL * 256];
__device__ __align__(256) float g_wc1 [3 * DIN * 256];
__device__ __align__(256) float g_wc2 [3 * 256 * 256];

__device__ __forceinline__ float to_tf32(float x) {
    asm("cvt.rna.tf32.f32 %0, %0;" : "+f"(x));
    return x;
}

// fragment-order index for B[k][n] in a [K x N] matrix
__device__ __forceinline__ size_t fidx(int k, int n, int N) {
    return ((size_t)(k >> 3) * (N >> 3) + (n >> 3)) * 64
         + (size_t)(((n & 7) * 4 + (k & 3)) * 2 + ((k >> 2) & 1));
}

__device__ __forceinline__ void cp16(uint32_t dst, const float* src, bool ok) {
    const int sz = ok ? 16 : 0;
    asm volatile("cp.async.cg.shared.global [%0], [%1], 16, %2;\n"
                 :: "r"(dst), "l"(src), "r"(sz));
}
__device__ __forceinline__ void cp_commit() {
    asm volatile("cp.async.commit_group;\n");
}
__device__ __forceinline__ void cp_wait1() {
    asm volatile("cp.async.wait_group 1;\n");
}
__device__ __forceinline__ void ldsm4(uint32_t* r, uint32_t addr) {
    asm volatile("ldmatrix.sync.aligned.m8n8.x4.shared.b16 {%0,%1,%2,%3}, [%4];"
                 : "=r"(r[0]), "=r"(r[1]), "=r"(r[2]), "=r"(r[3]) : "r"(addr));
}

// ---------------------------------------------------------------------------
// merged pack kernels (2 launches)
// ---------------------------------------------------------------------------
#define SZ_QKV (NLAYER * DMODEL * QKVN)
#define SZ_WO  (NLAYER * DMODEL * DMODEL)
#define SZ_FF1 (NLAYER * DMODEL * 128)
#define SZ_FF2 (NLAYER * 128 * DMODEL)
#define SZ_FC  (DMODEL * 256)
#define SZ_LIN (SZ_QKV + SZ_WO + SZ_FF1 + SZ_FF2 + SZ_FC)

__global__ __launch_bounds__(256) void pack_linear_kernel(
    const float* __restrict__ Wq, const float* __restrict__ Wk,
    const float* __restrict__ Wv, const float* __restrict__ Wo,
    const float* __restrict__ F1, const float* __restrict__ F2,
    const float* __restrict__ FC,
    float* __restrict__ wqkv, float* __restrict__ wo,
    float* __restrict__ wf1, float* __restrict__ wf2, float* __restrict__ wfc)
{
    int i = blockIdx.x * 256 + threadIdx.x;
    if (i < SZ_QKV) {
        const int l = i / (DMODEL * QKVN);
        const int rem = i - l * DMODEL * QKVN;
        const int k = rem / QKVN, np = rem - k * QKVN;
        const float* W = (np < DMODEL) ? Wq : (np < 2 * DMODEL) ? Wk : Wv;
        const float v = W[(size_t)l * DMODEL * DMODEL + (size_t)k * DMODEL + (np % DMODEL)];
        wqkv[(size_t)l * DMODEL * QKVN + fidx(k, np, QKVN)] = to_tf32(v);
        return;
    }
    i -= SZ_QKV;
    if (i < SZ_WO) {
        const int l = i / (DMODEL * DMODEL);
        const int rem = i - l * DMODEL * DMODEL;
        const int k = rem / DMODEL, n = rem - k * DMODEL;
        wo[(size_t)l * DMODEL * DMODEL + fidx(k, n, DMODEL)] = to_tf32(Wo[i]);
        return;
    }
    i -= SZ_WO;
    if (i < SZ_FF1) {
        const int l = i / (DMODEL * 128);
        const int rem = i - l * DMODEL * 128;
        const int k = rem / 128, n = rem - k * 128;
        wf1[(size_t)l * DMODEL * 128 + fidx(k, n, 128)] = to_tf32(F1[i]);
        return;
    }
    i -= SZ_FF1;
    if (i < SZ_FF2) {
        const int l = i / (128 * DMODEL);
        const int rem = i - l * 128 * DMODEL;
        const int k = rem / DMODEL, n = rem - k * DMODEL;
        wf2[(size_t)l * 128 * DMODEL + fidx(k, n, DMODEL)] = to_tf32(F2[i]);
        return;
    }
    i -= SZ_FF2;
    if (i < SZ_FC) {
        const int k = i / 256, n = i - k * 256;
        wfc[fidx(k, n, 256)] = to_tf32(FC[i]);
    }
}

__global__ __launch_bounds__(256) void pack_conv_kernel(
    const float* __restrict__ W1, const float* __restrict__ W2,
    float* __restrict__ wc1, float* __restrict__ wc2)
{
    int i = blockIdx.x * 256 + threadIdx.x;
    if (i < 3 * DIN * 256) {
        const int n = i / (DIN * 3);
        const int r = i - n * (DIN * 3);
        const int k = r / 3, t = r - k * 3;
        wc1[fidx(t * DIN + k, n, 256)] = to_tf32(W1[i]);
        return;
    }
    i -= 3 * DIN * 256;
    if (i < 3 * 256 * 256) {
        const int n = i / (256 * 3);
        const int r = i - n * (256 * 3);
        const int k = r / 3, t = r - k * 3;
        wc2[fidx(t * 256 + k, n, 256)] = to_tf32(W2[i]);
    }
}

// ---------------------------------------------------------------------------
// pool + cos-sim (unchanged; correct since R2)
// ---------------------------------------------------------------------------
__global__ __launch_bounds__(256) void pool_sim_kernel(
    const float* __restrict__ x,
    const float* __restrict__ cos_w, const float* __restrict__ cos_b,
    const float* __restrict__ attn_w, const float* __restrict__ attn_b,
    float* __restrict__ pooled, float* __restrict__ outbuf)
{
    extern __shared__ float xs[];
    const int m   = blockIdx.x;
    const int tid = threadIdx.x;
    const float* xr = x + (size_t)m * 8 * DIN;

#pragma unroll
    for (int r = 0; r < 16; r++) {
        const int idx = tid + r * 256;
        *reinterpret_cast<float4*>(xs + idx * 4) =
            *reinterpret_cast<const float4*>(xr + idx * 4);
    }
    __syncthreads();

    float g12[16], g11[10], g22[10], sw[8], ad[8];
#pragma unroll
    for (int i = 0; i < 16; i++) g12[i] = 0.f;
#pragma unroll
    for (int i = 0; i < 10; i++) { g11[i] = 0.f; g22[i] = 0.f; }
#pragma unroll
    for (int i = 0; i < 8; i++)  { sw[i] = 0.f; ad[i] = 0.f; }

    for (int d = tid; d < DIN; d += 256) {
        float xv[8];
#pragma unroll
        for (int w = 0; w < 8; w++) xv[w] = xs[w * DIN + d];
        const float aw = attn_w[d];
#pragma unroll
        for (int w = 0; w < 8; w++) { sw[w] += xv[w]; ad[w] += xv[w] * aw; }
#pragma unroll
        for (int i = 0; i < 4; i++)
#pragma unroll
            for (int j = 0; j < 4; j++)
                g12[i * 4 + j] += xv[i] * xv[4 + j];
#pragma unroll
        for (int i = 0; i < 4; i++)
#pragma unroll
            for (int j = i; j < 4; j++) {
                const int t = i * (7 - i) / 2 + j;
                g11[t] += xv[i] * xv[j];
                g22[t] += xv[4 + i] * xv[4 + j];
            }
    }

    __shared__ float red[52][8];
    __shared__ float fin[52];
    __shared__ float aprob[8];
    const int lane = tid & 31, wid = tid >> 5;

#define WREDUCE(arr, n, off)                                              \
    _Pragma("unroll")                                                     \
    for (int i = 0; i < n; i++) {                                         \
        float v = arr[i];                                                 \
        _Pragma("unroll")                                                 \
        for (int o = 16; o; o >>= 1) v += __shfl_xor_sync(0xffffffffu, v, o); \
        if (lane == 0) red[off + i][wid] = v;                             \
    }
    WREDUCE(g12, 16, 0)
    WREDUCE(g11, 10, 16)
    WREDUCE(g22, 10, 26)
    WREDUCE(sw,   8, 36)
    WREDUCE(ad,   8, 44)
#undef WREDUCE
    __syncthreads();
    if (tid < 52) {
        float t = 0.f;
#pragma unroll
        for (int w = 0; w < 8; w++) t += red[tid][w];
        fin[tid] = t;
    }
    __syncthreads();

    if (tid == 0) {
        const float ab = attn_b[0];
        float sc[8], mx = -1e30f;
#pragma unroll
        for (int w = 0; w < 8; w++) { sc[w] = fin[44 + w] + ab; mx = fmaxf(mx, sc[w]); }
        float s = 0.f;
#pragma unroll
        for (int w = 0; w < 8; w++) { sc[w] = expf(sc[w] - mx); s += sc[w]; }
        const float inv = 1.f / s;
#pragma unroll
        for (int w = 0; w < 8; w++) aprob[w] = sc[w] * inv;
    }

    if (tid < 128) {
        float cw[4];
#pragma unroll
        for (int w = 0; w < 4; w++) cw[w] = cos_w[tid * 4 + w];
        const float cb = cos_b[tid];
        float d12 = 0.f, q1 = 0.f, q2 = 0.f, cs1 = 0.f, cs2 = 0.f;
#pragma unroll
        for (int i = 0; i < 4; i++)
#pragma unroll
            for (int j = 0; j < 4; j++)
                d12 += cw[i] * cw[j] * fin[i * 4 + j];
#pragma unroll
        for (int i = 0; i < 4; i++)
#pragma unroll
            for (int j = i; j < 4; j++) {
                const int t = i * (7 - i) / 2 + j;
                const float c2 = cw[i] * cw[j] * ((i == j) ? 1.f : 2.f);
                q1 += c2 * fin[16 + t];
                q2 += c2 * fin[26 + t];
            }
#pragma unroll
        for (int w = 0; w < 4; w++) {
            cs1 += cw[w] * fin[36 + w];
            cs2 += cw[w] * fin[40 + w];
        }
        d12 += cb * (cs1 + cs2) + (float)DIN * cb * cb;
        q1  += 2.f * cb * cs1 + (float)DIN * cb * cb;
        q2  += 2.f * cb * cs2 + (float)DIN * cb * cb;
        const float n1 = fmaxf(sqrtf(q1), 1e-8f);
        const float n2 = fmaxf(sqrtf(q2), 1e-8f);
        outbuf[(size_t)m * DMODEL + 512 + tid] = d12 / (n1 * n2);
    }
    __syncthreads();

    float a[8];
#pragma unroll
    for (int w = 0; w < 8; w++) a[w] = aprob[w];
    for (int d = tid; d < DIN; d += 256) {
        float p = 0.f;
#pragma unroll
        for (int w = 0; w < 8; w++) p += a[w] * xs[w * DIN + d];
        pooled[(size_t)m * DIN + d] = p;
    }
}

// ---------------------------------------------------------------------------
// tf32 tensor-core GEMM. BM x BN, BK=32, 3-stage cp.async, ldmatrix A frags.
// ---------------------------------------------------------------------------
template<int BM, int BN, bool CONV>
__global__ __launch_bounds__(256, (BM == 64 ? 3 : 2)) void gemm_tc(
    const float* __restrict__ A, int lda,
    const float* __restrict__ Bp,
    const float* __restrict__ bias,
    float* __restrict__ C, int ldc,
    int N, int K, int klog2, int flags)
{
    constexpr int NTB = BN / 8;
    constexpr int WNW = 8 / (BM / 32);
    constexpr int NT  = NTB / WNW;
    constexpr int A4  = BM / 32;
    constexpr int B4  = BN / 32;
    constexpr int ASZ = BM * 32;
    constexpr int BSZ = BN * 32;

    extern __shared__ float sm[];
    float* Asm = sm;
    float* Bsm = sm + 3 * ASZ;

    const uint32_t a_smem = (uint32_t)__cvta_generic_to_shared(Asm);
    const uint32_t b_smem = (uint32_t)__cvta_generic_to_shared(Bsm);

    const int tid  = threadIdx.x;
    const int lane = tid & 31;
    const int w    = tid >> 5;
    const int bm   = blockIdx.y * BM;
    const int bn   = blockIdx.x * BN;
    const int mtw  = (w / WNW) * 2;
    const int ntw  = (w % WNW) * NT;
    const int g    = lane >> 2, tg = lane & 3;
    const int ntiles = N >> 3;
    const int kmask = CONV ? ((1 << klog2) - 1) : 0;

    // ldmatrix per-thread geometry: tile t = lane>>3 (0..3), row-in-tile lane&7
    const int lt   = lane >> 3;
    const int tsel = lt >> 1;              // chunk half (0: cols k..k+3, 1: +4)
    const int rsel = (lt & 1) << 3;        // +8 rows for tiles 1,3
    int aoff[2], arx[2];
#pragma unroll
    for (int mi = 0; mi < 2; mi++) {
        const int row = (mtw + mi) * 16 + rsel + (lane & 7);
        aoff[mi] = row * 128;              // bytes (32 floats per row)
        arx[mi]  = row & 7;                // 16B-chunk XOR swizzle key
    }

    float acc[2][NT][4];
#pragma unroll
    for (int i = 0; i < 2; i++)
#pragma unroll
        for (int j = 0; j < NT; j++)
#pragma unroll
            for (int r = 0; r < 4; r++) acc[i][j][r] = 0.f;

    auto issue = [&](int st, int k0) {
        const int t   = CONV ? (k0 >> klog2) : 0;
        const int kr0 = CONV ? (k0 & kmask) : k0;
        const uint32_t as = a_smem + (uint32_t)(st * ASZ * 4);
#pragma unroll
        for (int r = 0; r < A4; r++) {
            const int idx = tid + r * 256;
            const int mm  = idx >> 3, cg = (idx & 7) << 2;
            const int gm  = bm + mm;
            const int swc = cg ^ ((mm & 7) << 2);
            bool ok = true;
            const float* src;
            if (CONV) {
                ok  = ((unsigned)((gm & (NB - 1)) + t - 1) < (unsigned)NB);
                src = ok ? (A + (size_t)(gm + t - 1) * lda + kr0 + cg) : A;
            } else {
                src = A + (size_t)gm * lda + kr0 + cg;
            }
            cp16(as + (uint32_t)((mm * 32 + swc) * 4), src, ok);
        }
        const int kt0 = k0 >> 3;
        const uint32_t bs = b_smem + (uint32_t)(st * BSZ * 4);
#pragma unroll
        for (int r = 0; r < B4; r++) {
            const int idx   = tid + r * 256;
            const int kbIdx = idx / (2 * BN);
            const int wi    = idx - kbIdx * 2 * BN;
            const float* src = Bp
                + (((size_t)(kt0 + kbIdx) * ntiles + (bn >> 3)) << 6) + (wi << 2);
            cp16(bs + (uint32_t)(idx << 4), src, true);
        }
    };

    const int kiters = K >> 5;
    issue(0, 0);
    cp_commit();
    if (kiters > 1) issue(1, 32);
    cp_commit();

    for (int i = 0; i < kiters; i++) {
        cp_wait1();
        __syncthreads();
        const int inext = i + 2;
        if (inext < kiters) {
            int stn = inext - (inext / 3) * 3;
            issue(stn, inext * 32);
        }
        cp_commit();

        const int st = i - (i / 3) * 3;
        const uint32_t as_sh = a_smem + (uint32_t)(st * ASZ * 4);
        const float* bs = Bsm + st * BSZ;
#pragma unroll
        for (int kb = 0; kb < 4; kb++) {
            uint32_t a[2][4];
#pragma unroll
            for (int mi = 0; mi < 2; mi++) {
                const uint32_t addr = as_sh + (uint32_t)aoff[mi]
                    + (uint32_t)(((((kb << 1) | tsel)) ^ arx[mi]) << 4);
                ldsm4(a[mi], addr);
            }
            float2 bf[NT];
#pragma unroll
            for (int nj = 0; nj < NT; nj++)
                bf[nj] = *reinterpret_cast<const float2*>(
                    &bs[(kb * NTB + ntw + nj) * 64 + lane * 2]);
#pragma unroll
            for (int mi = 0; mi < 2; mi++)
#pragma unroll
                for (int nj = 0; nj < NT; nj++)
                    asm volatile(
                        "mma.sync.aligned.m16n8k8.row.col.f32.tf32.tf32.f32 "
                        "{%0,%1,%2,%3}, {%4,%5,%6,%7}, {%8,%9}, {%0,%1,%2,%3};\n"
                        : "+f"(acc[mi][nj][0]), "+f"(acc[mi][nj][1]),
                          "+f"(acc[mi][nj][2]), "+f"(acc[mi][nj][3])
                        : "r"(a[mi][0]), "r"(a[mi][1]),
                          "r"(a[mi][2]), "r"(a[mi][3]),
                          "r"(__float_as_uint(bf[nj].x)), "r"(__float_as_uint(bf[nj].y)));
        }
    }

    // epilogue (float2 stores)
#pragma unroll
    for (int mi = 0; mi < 2; mi++) {
        const int r0 = bm + (mtw + mi) * 16 + g;
#pragma unroll
        for (int nj = 0; nj < NT; nj++) {
            const int c0 = bn + (ntw + nj) * 8 + tg * 2;
            const float bx = bias ? bias[c0]     : 0.f;
            const float by = bias ? bias[c0 + 1] : 0.f;
#pragma unroll
            for (int hh = 0; hh < 2; hh++) {
                float vx = acc[mi][nj][hh * 2]     + bx;
                float vy = acc[mi][nj][hh * 2 + 1] + by;
                if (flags & 1) { vx = fmaxf(vx, 0.f); vy = fmaxf(vy, 0.f); }
                *reinterpret_cast<float2*>(
                    C + (size_t)(r0 + hh * 8) * ldc + c0) = make_float2(vx, vy);
            }
        }
    }
}

// ---------------------------------------------------------------------------
// Banded local attention, smem-staged (one block per token, 8 warps = heads).
// ---------------------------------------------------------------------------
__global__ __launch_bounds__(256) void banded_attn_kernel(
    const float* __restrict__ qkv, float* __restrict__ ctx)
{
    __shared__ float qs[DMODEL];
    __shared__ float ks[3][DMODEL];
    __shared__ float vs[3][DMODEL];

    const int m   = blockIdx.x;
    const int tid = threadIdx.x;
    const int n   = m & (NB - 1);

    for (int idx = tid; idx < 7 * 160; idx += 256) {
        const int seg = idx / 160;
        const int off = idx - seg * 160;
        float4 val = make_float4(0.f, 0.f, 0.f, 0.f);
        float* dst;
        if (seg == 0) {
            val = *reinterpret_cast<const float4*>(qkv + (size_t)m * QKVN + off * 4);
            dst = qs + off * 4;
        } else {
            const int j     = (seg - 1) % 3;
            const int which = (seg - 1) / 3;
            const int nn = n + j - 1;
            if ((unsigned)nn < (unsigned)NB)
                val = *reinterpret_cast<const float4*>(
                    qkv + (size_t)(m + j - 1) * QKVN + (which ? 2 * DMODEL : DMODEL) + off * 4);
            dst = (which ? vs[j] : ks[j]) + off * 4;
        }
        *reinterpret_cast<float4*>(dst) = val;
    }
    __syncthreads();

    const int h    = tid >> 5;
    const int lane = tid & 31;
    const float scale = 0.11180339887498949f;
    const int base = h * 80;

    const float qv0 = qs[base + lane];
    const float qv1 = qs[base + lane + 32];
    const float qv2 = (lane < 16) ? qs[base + lane + 64] : 0.f;

    bool val3[3];
    float s[3];
#pragma unroll
    for (int j = 0; j < 3; j++) {
        const int nn = n + j - 1;
        val3[j] = ((unsigned)nn < (unsigned)NB);
        float acc = qv0 * ks[j][base + lane] + qv1 * ks[j][base + lane + 32];
        if (lane < 16) acc += qv2 * ks[j][base + lane + 64];
#pragma unroll
        for (int o = 16; o; o >>= 1) acc += __shfl_xor_sync(0xffffffffu, acc, o);
        s[j] = val3[j] ? acc * scale : -1e30f;
    }

    const float mx = fmaxf(s[0], fmaxf(s[1], s[2]));
    float e[3], sum = 0.f;
#pragma unroll
    for (int j = 0; j < 3; j++) {
        e[j] = val3[j] ? expf(s[j] - mx) : 0.f;
        sum += e[j];
    }
    const float inv = 1.f / sum;

    float o0 = 0.f, o1 = 0.f, o2 = 0.f;
#pragma unroll
    for (int j = 0; j < 3; j++) {
        const float p = e[j] * inv;
        o0 += p * vs[j][base + lane];
        o1 += p * vs[j][base + lane + 32];
        if (lane < 16) o2 += p * vs[j][base + lane + 64];
    }
    float* cp = ctx + (size_t)m * DMODEL + base;
    cp[lane]      = o0;
    cp[lane + 32] = o1;
    if (lane < 16) cp[lane + 64] = o2;
}

// ---------------------------------------------------------------------------
// warp-per-row residual + LayerNorm
// ---------------------------------------------------------------------------
__global__ __launch_bounds__(256) void residual_ln_kernel(
    float* __restrict__ out, const float* __restrict__ add,
    const float* __restrict__ g, const float* __restrict__ b)
{
    const int row  = blockIdx.x * 8 + (threadIdx.x >> 5);
    const int lane = threadIdx.x & 31;

    const float4* o4 = reinterpret_cast<const float4*>(out + (size_t)row * DMODEL);
    const float4* a4 = reinterpret_cast<const float4*>(add + (size_t)row * DMODEL);

    float4 v[5];
    float s = 0.f;
#pragma unroll
    for (int i = 0; i < 5; i++) {
        const float4 ov = o4[i * 32 + lane];
        const float4 av = a4[i * 32 + lane];
        v[i] = make_float4(ov.x + av.x, ov.y + av.y, ov.z + av.z, ov.w + av.w);
        s += v[i].x + v[i].y + v[i].z + v[i].w;
    }
#pragma unroll
    for (int o = 16; o; o >>= 1) s += __shfl_xor_sync(0xffffffffu, s, o);
    const float mean = s * (1.f / (float)DMODEL);

    float vs = 0.f;
#pragma unroll
    for (int i = 0; i < 5; i++) {
        const float dx = v[i].x - mean, dy = v[i].y - mean;
        const float dz = v[i].z - mean, dw = v[i].w - mean;
        vs += dx * dx + dy * dy + dz * dz + dw * dw;
    }
#pragma unroll
    for (int o = 16; o; o >>= 1) vs += __shfl_xor_sync(0xffffffffu, vs, o);
    const float rstd = rsqrtf(vs * (1.f / (float)DMODEL) + 1e-5f);

    float4* w4 = reinterpret_cast<float4*>(out + (size_t)row * DMODEL);
    const float4* g4 = reinterpret_cast<const float4*>(g);
    const float4* b4 = reinterpret_cast<const float4*>(b);
#pragma unroll
    for (int i = 0; i < 5; i++) {
        const float4 gv = g4[i * 32 + lane];
        const float4 bv = b4[i * 32 + lane];
        w4[i * 32 + lane] = make_float4(
            (v[i].x - mean) * rstd * gv.x + bv.x,
            (v[i].y - mean) * rstd * gv.y + bv.y,
            (v[i].z - mean) * rstd * gv.z + bv.z,
            (v[i].w - mean) * rstd * gv.w + bv.w);
    }
}

// ---------------------------------------------------------------------------
__global__ __launch_bounds__(256) void cls_kernel(
    const float* __restrict__ h, const float* __restrict__ w,
    const float* __restrict__ b, float* __restrict__ out)
{
    const int gw   = (blockIdx.x * 256 + threadIdx.x) >> 5;
    const int lane = threadIdx.x & 31;
    if (gw >= MROWS) return;
    float a0 = 0.f, a1 = 0.f;
#pragma unroll
    for (int i = 0; i < 8; i++) {
        const int k = lane + i * 32;
        const float hv = h[(size_t)gw * 256 + k];
        a0 += hv * w[k * 2];
        a1 += hv * w[k * 2 + 1];
    }
#pragma unroll
    for (int o = 16; o; o >>= 1) {
        a0 += __shfl_xor_sync(0xffffffffu, a0, o);
        a1 += __shfl_xor_sync(0xffffffffu, a1, o);
    }
    if (lane == 0) {
        out[(size_t)gw * 2]     = a0 + b[0];
        out[(size_t)gw * 2 + 1] = a1 + b[1];
    }
}

// ---------------------------------------------------------------------------
extern "C" void kernel_launch(void* const* d_in, const int* in_sizes, int n_in,
                              void* d_out, int out_size)
{
    const float* x       = (const float*)d_in[0];
    const float* cos_w   = (const float*)d_in[2];
    const float* cos_b   = (const float*)d_in[3];
    const float* attn_w  = (const float*)d_in[4];
    const float* attn_b  = (const float*)d_in[5];
    const float* conv1_w = (const float*)d_in[6];
    const float* conv1_b = (const float*)d_in[7];
    const float* conv2_w = (const float*)d_in[8];
    const float* conv2_b = (const float*)d_in[9];
    const float* Wq      = (const float*)d_in[10];
    const float* Wk      = (const float*)d_in[11];
    const float* Wv      = (const float*)d_in[12];
    const float* Wo      = (const float*)d_in[13];
    const float* ln1_g   = (const float*)d_in[14];
    const float* ln1_b   = (const float*)d_in[15];
    const float* ff1_w   = (const float*)d_in[16];
    const float* ff1_b   = (const float*)d_in[17];
    const float* ff2_w   = (const float*)d_in[18];
    const float* ff2_b   = (const float*)d_in[19];
    const float* ln2_g   = (const float*)d_in[20];
    const float* ln2_b   = (const float*)d_in[21];
    const float* fc_w    = (const float*)d_in[22];
    const float* fc_b    = (const float*)d_in[23];
    const float* cls_w   = (const float*)d_in[24];
    const float* cls_b   = (const float*)d_in[25];
    float* logits = (float*)d_out;

    float *pooled, *obuf, *qkvb, *ctxb, *tmpb, *ffb, *hb;
    float *wqkv, *wo, *wf1, *wf2, *wfc, *wc1, *wc2;
    cudaGetSymbolAddress((void**)&pooled, g_pooled);
    cudaGetSymbolAddress((void**)&obuf,   g_out);
    cudaGetSymbolAddress((void**)&qkvb,   g_qkv);
    cudaGetSymbolAddress((void**)&ctxb,   g_ctx);
    cudaGetSymbolAddress((void**)&tmpb,   g_tmp);
    cudaGetSymbolAddress((void**)&ffb,    g_ff);
    cudaGetSymbolAddress((void**)&hb,     g_h);
    cudaGetSymbolAddress((void**)&wqkv,   g_wqkv);
    cudaGetSymbolAddress((void**)&wo,     g_wo);
    cudaGetSymbolAddress((void**)&wf1,    g_wf1);
    cudaGetSymbolAddress((void**)&wf2,    g_wf2);
    cudaGetSymbolAddress((void**)&wfc,    g_wfc);
    cudaGetSymbolAddress((void**)&wc1,    g_wc1);
    cudaGetSymbolAddress((void**)&wc2,    g_wc2);

    const int smemQKV = 3 * (128 * 32 + 128 * 32) * 4;  // 98304
    const int smem128 = 3 * (64 * 32 + 128 * 32) * 4;   // 73728
    const int smem64  = 3 * (64 * 32 + 64 * 32) * 4;    // 49152

    cudaFuncSetAttribute(pool_sim_kernel,
                         cudaFuncAttributeMaxDynamicSharedMemorySize, 65536);
    cudaFuncSetAttribute(gemm_tc<128, 128, false>,
                         cudaFuncAttributeMaxDynamicSharedMemorySize, smemQKV);
    cudaFuncSetAttribute(gemm_tc<64, 128, false>,
                         cudaFuncAttributeMaxDynamicSharedMemorySize, smem128);
    cudaFuncSetAttribute(gemm_tc<64, 64, false>,
                         cudaFuncAttributeMaxDynamicSharedMemorySize, smem64);
    cudaFuncSetAttribute(gemm_tc<64, 64, true>,
                         cudaFuncAttributeMaxDynamicSharedMemorySize, smem64);

    // 0. pack weights
    pack_linear_kernel<<<(SZ_LIN + 255) / 256, 256>>>(
        Wq, Wk, Wv, Wo, ff1_w, ff2_w, fc_w, wqkv, wo, wf1, wf2, wfc);
    pack_conv_kernel<<<(3 * DIN * 256 + 3 * 256 * 256 + 255) / 256, 256>>>(
        conv1_w, conv2_w, wc1, wc2);

    // 1. pooling + cos-sim
    pool_sim_kernel<<<MROWS, 256, 65536>>>(x, cos_w, cos_b, attn_w, attn_b,
                                           pooled, obuf);

    // 2. conv1: K' = 6144
    gemm_tc<64, 64, true><<<dim3(4, 64), 256, smem64>>>(
        pooled, DIN, wc1, conv1_b, obuf, DMODEL, 256, 3 * DIN, 11, 1);

    // 3. conv2: K' = 768
    gemm_tc<64, 64, true><<<dim3(4, 64), 256, smem64>>>(
        obuf, DMODEL, wc2, conv2_b, obuf + 256, DMODEL, 256, 3 * 256, 8, 1);

    // 4. transformer layers
    for (int l = 0; l < NLAYER; l++) {
        gemm_tc<128, 128, false><<<dim3(15, 32), 256, smemQKV>>>(
            obuf, DMODEL, wqkv + (size_t)l * DMODEL * QKVN,
            nullptr, qkvb, QKVN, QKVN, DMODEL, 0, 0);

        banded_attn_kernel<<<MROWS, 256>>>(qkvb, ctxb);

        gemm_tc<64, 128, false><<<dim3(5, 64), 256, smem128>>>(
            ctxb, DMODEL, wo + (size_t)l * DMODEL * DMODEL,
            nullptr, tmpb, DMODEL, DMODEL, DMODEL, 0, 0);
        residual_ln_kernel<<<MROWS / 8, 256>>>(obuf, tmpb,
                                               ln1_g + l * DMODEL, ln1_b + l * DMODEL);

        gemm_tc<64, 64, false><<<dim3(2, 64), 256, smem64>>>(
            obuf, DMODEL, wf1 + (size_t)l * DMODEL * 128,
            ff1_b + l * 128, ffb, 128, 128, DMODEL, 0, 1);
        gemm_tc<64, 128, false><<<dim3(5, 64), 256, smem128>>>(
            ffb, 128, wf2 + (size_t)l * 128 * DMODEL,
            ff2_b + l * DMODEL, tmpb, DMODEL, DMODEL, 128, 0, 0);
        residual_ln_kernel<<<MROWS / 8, 256>>>(obuf, tmpb,
                                               ln2_g + l * DMODEL, ln2_b + l * DMODEL);
    }

    // 5. head
    gemm_tc<64, 64, false><<<dim3(4, 64), 256, smem64>>>(
        obuf, DMODEL, wfc, fc_b, hb, 256, 256, DMODEL, 0, 1);
    cls_kernel<<<(MROWS * 32 + 255) / 256, 256>>>(hb, cls_w, cls_b, logits);
}